// round 11
// baseline (speedup 1.0000x reference)
#include <cuda_runtime.h>
#include <cuda_bf16.h>
#include <math.h>
#include <stdint.h>

#define B 8
#define C 128
#define NN 2048
#define MM 512

// ---------------- scratch ----------------
__device__ __nv_bfloat16 g_qh[B * NN * C];
__device__ __nv_bfloat16 g_qm[B * NN * C];
__device__ __nv_bfloat16 g_ql[B * NN * C];
__device__ __nv_bfloat16 g_kh[B * NN * C];
__device__ __nv_bfloat16 g_km[B * NN * C];
__device__ __nv_bfloat16 g_kl[B * NN * C];
__device__ __nv_bfloat16 g_vh[B * C * NN];
__device__ __nv_bfloat16 g_vl[B * C * NN];
__device__ float g_E[(size_t)B * NN * NN];
__device__ float g_rowmax[B * NN];
__device__ float g_rowsum[B * NN];
__device__ float g_selpart[B * 128 * NN];
__device__ float g_sel[B * NN];
__device__ int   g_idx[B * MM];
__device__ float g_outpart[4][B * C * MM];

__device__ __forceinline__ uint32_t smem_u32(const void* p) {
    uint32_t a;
    asm("{ .reg .u64 t; cvta.to.shared.u64 t, %1; cvt.u32.u64 %0, t; }" : "=r"(a) : "l"(p));
    return a;
}
__device__ __forceinline__ void ldsm_x4(uint32_t* r, uint32_t a) {
    asm volatile("ldmatrix.sync.aligned.m8n8.x4.shared.b16 {%0,%1,%2,%3}, [%4];"
        : "=r"(r[0]), "=r"(r[1]), "=r"(r[2]), "=r"(r[3]) : "r"(a));
}
__device__ __forceinline__ void ldsm_x2(uint32_t* r, uint32_t a) {
    asm volatile("ldmatrix.sync.aligned.m8n8.x2.shared.b16 {%0,%1}, [%2];"
        : "=r"(r[0]), "=r"(r[1]) : "r"(a));
}
__device__ __forceinline__ void mma_bf16(float* d, const uint32_t* a, const uint32_t* b) {
    asm volatile("mma.sync.aligned.m16n8k16.row.col.f32.bf16.bf16.f32 "
        "{%0,%1,%2,%3}, {%4,%5,%6,%7}, {%8,%9}, {%0,%1,%2,%3};"
        : "+f"(d[0]), "+f"(d[1]), "+f"(d[2]), "+f"(d[3])
        : "r"(a[0]), "r"(a[1]), "r"(a[2]), "r"(a[3]), "r"(b[0]), "r"(b[1]));
}

// ---------------- kernel 1: q,k,v = W @ x; q,k split h/m/l to [N][C]; v split h/l -------
__global__ __launch_bounds__(256) void qkv_kernel(const float* __restrict__ x,
                                                  const float* __restrict__ Wq,
                                                  const float* __restrict__ Wk,
                                                  const float* __restrict__ Wv) {
    extern __shared__ float sm[];
    float* Ws = sm;
    float* xs = sm + C * C;
    const int b  = blockIdx.y;
    const int n0 = blockIdx.x * 64;
    const float* W = blockIdx.z == 0 ? Wq : (blockIdx.z == 1 ? Wk : Wv);
    const int t = threadIdx.x;

    for (int i = t; i < C * C; i += 256) Ws[i] = W[i];
    const float* xb = x + (size_t)b * C * NN;
    for (int i = t; i < C * 64; i += 256) {
        int c = i >> 6, n = i & 63;
        xs[i] = xb[(size_t)c * NN + n0 + n];
    }
    __syncthreads();

    const int tx = t & 15, ty = t >> 4;
    float acc[8][4];
#pragma unroll
    for (int i = 0; i < 8; i++)
#pragma unroll
        for (int j = 0; j < 4; j++) acc[i][j] = 0.f;

    for (int c = 0; c < C; c++) {
        float4 xv = *(const float4*)&xs[c * 64 + tx * 4];
#pragma unroll
        for (int i = 0; i < 8; i++) {
            float w = Ws[(ty * 8 + i) * C + c];
            acc[i][0] = fmaf(w, xv.x, acc[i][0]);
            acc[i][1] = fmaf(w, xv.y, acc[i][1]);
            acc[i][2] = fmaf(w, xv.z, acc[i][2]);
            acc[i][3] = fmaf(w, xv.w, acc[i][3]);
        }
    }

    if (blockIdx.z == 2) {
#pragma unroll
        for (int i = 0; i < 8; i++) {
            size_t o = ((size_t)b * C + ty * 8 + i) * NN + n0 + tx * 4;
            __nv_bfloat16 h[4], l[4];
#pragma unroll
            for (int j = 0; j < 4; j++) {
                h[j] = __float2bfloat16_rn(acc[i][j]);
                l[j] = __float2bfloat16_rn(acc[i][j] - __bfloat162float(h[j]));
            }
            *(__nv_bfloat162*)&g_vh[o]     = __nv_bfloat162(h[0], h[1]);
            *(__nv_bfloat162*)&g_vh[o + 2] = __nv_bfloat162(h[2], h[3]);
            *(__nv_bfloat162*)&g_vl[o]     = __nv_bfloat162(l[0], l[1]);
            *(__nv_bfloat162*)&g_vl[o + 2] = __nv_bfloat162(l[2], l[3]);
        }
    } else {
        __nv_bfloat16* dh = blockIdx.z == 0 ? g_qh : g_kh;
        __nv_bfloat16* dm = blockIdx.z == 0 ? g_qm : g_km;
        __nv_bfloat16* dl = blockIdx.z == 0 ? g_ql : g_kl;
#pragma unroll
        for (int j = 0; j < 4; j++) {
            __nv_bfloat16 h8[8], m8[8], l8[8];
#pragma unroll
            for (int i = 0; i < 8; i++) {
                float a = acc[i][j];
                __nv_bfloat16 h = __float2bfloat16_rn(a);
                float r1 = a - __bfloat162float(h);
                __nv_bfloat16 m = __float2bfloat16_rn(r1);
                float r2 = r1 - __bfloat162float(m);
                h8[i] = h; m8[i] = m; l8[i] = __float2bfloat16_rn(r2);
            }
            size_t o = ((size_t)b * NN + n0 + tx * 4 + j) * C + ty * 8;
            *(uint4*)&dh[o] = *(uint4*)h8;
            *(uint4*)&dm[o] = *(uint4*)m8;
            *(uint4*)&dl[o] = *(uint4*)l8;
        }
    }
}

// ---------------- kernel 2: E via bf16x6 mma.sync; 512 threads (b0 + blockIdx.z) --------
#define ST 40
#define MATB (128 * ST * 2)
#define BUFB (6 * MATB)
#define E_SMEM (2 * BUFB)

__device__ __forceinline__ void e_load_mat(uint32_t dst, const __nv_bfloat16* src, int t) {
    int r = t >> 2, k8 = t & 3;
    asm volatile("cp.async.cg.shared.global [%0], [%1], 16;"
        :: "r"(dst + (uint32_t)(r * ST + k8 * 8) * 2),
           "l"(src + (size_t)r * C + k8 * 8));
}

__global__ __launch_bounds__(512) void energy_bf16_kernel(int b0) {
    extern __shared__ char esm[];
    const uint32_t sb = smem_u32(esm);
    const int b = b0 + blockIdx.z, n0 = blockIdx.y * 128, m0 = blockIdx.x * 128;
    const int t = threadIdx.x, lane = t & 31, wid = t >> 5;
    const int wn = wid >> 2, wm = wid & 3;
    const int g = lane >> 2, tg = lane & 3;

    const __nv_bfloat16* Ah = g_qh + ((size_t)b * NN + n0) * C;
    const __nv_bfloat16* Am = g_qm + ((size_t)b * NN + n0) * C;
    const __nv_bfloat16* Al = g_ql + ((size_t)b * NN + n0) * C;
    const __nv_bfloat16* Bh = g_kh + ((size_t)b * NN + m0) * C;
    const __nv_bfloat16* Bm = g_km + ((size_t)b * NN + m0) * C;
    const __nv_bfloat16* Bl = g_kl + ((size_t)b * NN + m0) * C;

    const uint32_t laneA = (uint32_t)((lane & 15) * ST + (lane >> 4) * 8) * 2;
    const int l16 = lane & 15;
    const uint32_t laneB = (uint32_t)((l16 & 7) * ST + (l16 >> 3) * 8) * 2;

    float acc[2][4][4];
#pragma unroll
    for (int i = 0; i < 2; i++)
#pragma unroll
        for (int j = 0; j < 4; j++)
#pragma unroll
            for (int r = 0; r < 4; r++) acc[i][j][r] = 0.f;

    {
        uint32_t d0 = sb;
        e_load_mat(d0 + 0 * MATB, Ah, t);
        e_load_mat(d0 + 1 * MATB, Am, t);
        e_load_mat(d0 + 2 * MATB, Al, t);
        e_load_mat(d0 + 3 * MATB, Bh, t);
        e_load_mat(d0 + 4 * MATB, Bm, t);
        e_load_mat(d0 + 5 * MATB, Bl, t);
        asm volatile("cp.async.commit_group;" ::: "memory");
    }

    for (int ch = 0; ch < 4; ch++) {
        const int p = ch & 1;
        if (ch < 3) {
            const int c0 = (ch + 1) * 32;
            uint32_t d0 = sb + (p ^ 1) * BUFB;
            e_load_mat(d0 + 0 * MATB, Ah + c0, t);
            e_load_mat(d0 + 1 * MATB, Am + c0, t);
            e_load_mat(d0 + 2 * MATB, Al + c0, t);
            e_load_mat(d0 + 3 * MATB, Bh + c0, t);
            e_load_mat(d0 + 4 * MATB, Bm + c0, t);
            e_load_mat(d0 + 5 * MATB, Bl + c0, t);
            asm volatile("cp.async.commit_group;" ::: "memory");
            asm volatile("cp.async.wait_group 1;" ::: "memory");
        } else {
            asm volatile("cp.async.wait_group 0;" ::: "memory");
        }
        __syncthreads();

        const uint32_t base = sb + p * BUFB;
#pragma unroll
        for (int k0 = 0; k0 < 32; k0 += 16) {
            uint32_t bh[4][2], bm[4][2], bl[4][2];
#pragma unroll
            for (int j = 0; j < 4; j++) {
                uint32_t boff = (uint32_t)((wm * 32 + j * 8) * ST + k0) * 2 + laneB;
                ldsm_x2(bh[j], base + 3 * MATB + boff);
                ldsm_x2(bm[j], base + 4 * MATB + boff);
                ldsm_x2(bl[j], base + 5 * MATB + boff);
            }
#pragma unroll
            for (int i = 0; i < 2; i++) {
                uint32_t aoff = (uint32_t)((wn * 32 + i * 16) * ST + k0) * 2 + laneA;
                uint32_t ah[4], am[4], al[4];
                ldsm_x4(ah, base + 0 * MATB + aoff);
                ldsm_x4(am, base + 1 * MATB + aoff);
                ldsm_x4(al, base + 2 * MATB + aoff);
#pragma unroll
                for (int j = 0; j < 4; j++) {
                    mma_bf16(acc[i][j], ah, bh[j]);
                    mma_bf16(acc[i][j], ah, bm[j]);
                    mma_bf16(acc[i][j], am, bh[j]);
                    mma_bf16(acc[i][j], am, bm[j]);
                    mma_bf16(acc[i][j], ah, bl[j]);
                    mma_bf16(acc[i][j], al, bh[j]);
                }
            }
        }
        __syncthreads();
    }

    const float scale = 0.08838834764831845f;
    float* Eb = g_E + (size_t)b * NN * NN;
#pragma unroll
    for (int i = 0; i < 2; i++) {
        int row = n0 + wn * 32 + i * 16 + g;
#pragma unroll
        for (int j = 0; j < 4; j++) {
            int col = m0 + wm * 32 + j * 8 + tg * 2;
            *(float2*)&Eb[(size_t)row * NN + col] =
                make_float2(acc[i][j][0] * scale, acc[i][j][1] * scale);
            *(float2*)&Eb[(size_t)(row + 8) * NN + col] =
                make_float2(acc[i][j][2] * scale, acc[i][j][3] * scale);
        }
    }
}

// ---------------- kernel 3: row max/sumexp + partial col sums (b0 param) --------------
__global__ __launch_bounds__(256) void softscan_kernel(int b0) {
    __shared__ float redA[8], redB[8];
    const int b  = b0 + blockIdx.y;
    const int r0 = blockIdx.x * 16;
    const int t  = threadIdx.x;
    const int lane = t & 31, w = t >> 5;
    float colacc[8] = {0.f, 0.f, 0.f, 0.f, 0.f, 0.f, 0.f, 0.f};
    const float* Eb = g_E + (size_t)b * NN * NN;

    float vcur[8];
    {
        const float* Er = Eb + (size_t)r0 * NN;
#pragma unroll
        for (int k = 0; k < 8; k++) vcur[k] = Er[t + k * 256];
    }
    for (int r = 0; r < 16; r++) {
        const int n = r0 + r;
        float vnext[8];
        if (r < 15) {
            const float* Ern = Eb + (size_t)(n + 1) * NN;
#pragma unroll
            for (int k = 0; k < 8; k++) vnext[k] = Ern[t + k * 256];
        }
        float mx = -3.4e38f;
#pragma unroll
        for (int k = 0; k < 8; k++) mx = fmaxf(mx, vcur[k]);
#pragma unroll
        for (int o = 16; o; o >>= 1) mx = fmaxf(mx, __shfl_xor_sync(0xffffffffu, mx, o));
        if (lane == 0) redA[w] = mx;
        __syncthreads();
        mx = redA[0];
#pragma unroll
        for (int i = 1; i < 8; i++) mx = fmaxf(mx, redA[i]);

        float s = 0.f;
#pragma unroll
        for (int k = 0; k < 8; k++) {
            vcur[k] = __expf(vcur[k] - mx);
            s += vcur[k];
        }
#pragma unroll
        for (int o = 16; o; o >>= 1) s += __shfl_xor_sync(0xffffffffu, s, o);
        if (lane == 0) redB[w] = s;
        __syncthreads();
        s = redB[0];
#pragma unroll
        for (int i = 1; i < 8; i++) s += redB[i];

        if (t == 0) {
            g_rowmax[b * NN + n] = mx;
            g_rowsum[b * NN + n] = s;
        }
        float inv = 1.0f / s;
#pragma unroll
        for (int k = 0; k < 8; k++) colacc[k] += vcur[k] * inv;
        if (r < 15) {
#pragma unroll
            for (int k = 0; k < 8; k++) vcur[k] = vnext[k];
        }
    }
    float* part = g_selpart + ((size_t)b * 128 + blockIdx.x) * NN;
#pragma unroll
    for (int k = 0; k < 8; k++) part[t + k * 256] = colacc[k];
}

// ---------------- kernel 3b: reduce partials (R4-proven scalar config, b0) --------------
__global__ __launch_bounds__(128) void selsum_kernel(int b0) {
    const int b = b0 + blockIdx.y;
    const int m = blockIdx.x * 128 + threadIdx.x;
    const float* p = g_selpart + (size_t)b * 128 * NN;
    float s = 0.f;
#pragma unroll 8
    for (int i = 0; i < 128; i++) s += p[(size_t)i * NN + m];
    g_sel[b * NN + m] = s;
}

// ---------------- kernel 4: stable top-k via rank counting (b0) ----------------
__global__ __launch_bounds__(256) void topk_kernel(int b0) {
    __shared__ float s[NN];
    const int b = b0 + blockIdx.y;
    for (int i = threadIdx.x; i < NN; i += 256) s[i] = g_sel[b * NN + i];
    __syncthreads();
    const int i  = blockIdx.x * 256 + threadIdx.x;
    const float vi = s[i];
    int rank = 0;
#pragma unroll 4
    for (int j = 0; j < NN; j++) {
        float vj = s[j];
        rank += (vj > vi) || (vj == vi && j < i);
    }
    if (rank < MM) g_idx[b * MM + rank] = i;
}

// ---------------- kernel 5: output GEMM via bf16x3 mma.sync, split-K=4 (b0) ------------
#define ST2 72
#define OV_H 0
#define OV_L (128 * ST2 * 2)
#define OP_H (2 * 128 * ST2 * 2)
#define OP_L (OP_H + 64 * ST2 * 2)
#define O_SMEM (OP_L + 64 * ST2 * 2)

__global__ __launch_bounds__(256) void outgemm_tc_kernel(int b0) {
    extern __shared__ char osm[];
    __shared__ int   rows[64];
    __shared__ float rmax[64], rinv[64];
    const uint32_t sbase = smem_u32(osm);
    const int b = b0 + blockIdx.y, j0 = blockIdx.x * 64, z = blockIdx.z;
    const int t = threadIdx.x, lane = t & 31, wid = t >> 5;
    const int wc = wid & 3, wj = wid >> 2;
    const int g = lane >> 2, tg = lane & 3;

    if (t < 64) {
        int r   = g_idx[b * MM + j0 + t];
        rows[t] = r;
        rmax[t] = g_rowmax[b * NN + r];
        rinv[t] = 1.0f / g_rowsum[b * NN + r];
    }
    __syncthreads();

    const __nv_bfloat16* vh = g_vh + (size_t)b * C * NN;
    const __nv_bfloat16* vl = g_vl + (size_t)b * C * NN;
    const float* Eb = g_E + (size_t)b * NN * NN;

    const uint32_t laneA = (uint32_t)((lane & 15) * ST2 + (lane >> 4) * 8) * 2;
    const int l16 = lane & 15;
    const uint32_t laneB = (uint32_t)((l16 & 7) * ST2 + (l16 >> 3) * 8) * 2;

    float acc[2][4][4];
#pragma unroll
    for (int i = 0; i < 2; i++)
#pragma unroll
        for (int j = 0; j < 4; j++)
#pragma unroll
            for (int r = 0; r < 4; r++) acc[i][j][r] = 0.f;

    const int nBeg = z * (NN / 4);
    const int jj = t >> 2, q4 = t & 3;
    const float mxj = rmax[jj], ivj = rinv[jj];
    const size_t erow = (size_t)rows[jj] * NN;

    for (int n0 = nBeg; n0 < nBeg + NN / 4; n0 += 64) {
#pragma unroll
        for (int jld = 0; jld < 4; jld++) {
            int i = t + jld * 256;
            int c = i >> 3, k8 = i & 7;
            asm volatile("cp.async.cg.shared.global [%0], [%1], 16;"
                :: "r"(sbase + OV_H + (uint32_t)(c * ST2 + k8 * 8) * 2),
                   "l"(vh + (size_t)c * NN + n0 + k8 * 8));
            asm volatile("cp.async.cg.shared.global [%0], [%1], 16;"
                :: "r"(sbase + OV_L + (uint32_t)(c * ST2 + k8 * 8) * 2),
                   "l"(vl + (size_t)c * NN + n0 + k8 * 8));
        }
        asm volatile("cp.async.commit_group;" ::: "memory");

        {
            const float* Er = Eb + erow + n0 + q4 * 16;
#pragma unroll
            for (int i4 = 0; i4 < 4; i4++) {
                float4 e = *(const float4*)(Er + i4 * 4);
                float p0 = __expf(e.x - mxj) * ivj;
                float p1 = __expf(e.y - mxj) * ivj;
                float p2 = __expf(e.z - mxj) * ivj;
                float p3 = __expf(e.w - mxj) * ivj;
                __nv_bfloat16 h0 = __float2bfloat16_rn(p0);
                __nv_bfloat16 h1 = __float2bfloat16_rn(p1);
                __nv_bfloat16 h2 = __float2bfloat16_rn(p2);
                __nv_bfloat16 h3 = __float2bfloat16_rn(p3);
                __nv_bfloat16 l0 = __float2bfloat16_rn(p0 - __bfloat162float(h0));
                __nv_bfloat16 l1 = __float2bfloat16_rn(p1 - __bfloat162float(h1));
                __nv_bfloat16 l2 = __float2bfloat16_rn(p2 - __bfloat162float(h2));
                __nv_bfloat16 l3 = __float2bfloat16_rn(p3 - __bfloat162float(h3));
                uint32_t off = (uint32_t)(jj * ST2 + q4 * 16 + i4 * 4) * 2;
                *(__nv_bfloat162*)(osm + OP_H + off)     = __nv_bfloat162(h0, h1);
                *(__nv_bfloat162*)(osm + OP_H + off + 4) = __nv_bfloat162(h2, h3);
                *(__nv_bfloat162*)(osm + OP_L + off)     = __nv_bfloat162(l0, l1);
                *(__nv_bfloat162*)(osm + OP_L + off + 4) = __nv_bfloat162(l2, l3);
            }
        }
        asm volatile("cp.async.wait_group 0;" ::: "memory");
        __syncthreads();

#pragma unroll
        for (int k0 = 0; k0 < 64; k0 += 16) {
            uint32_t bh[4][2], bl[4][2];
#pragma unroll
            for (int nj = 0; nj < 4; nj++) {
                uint32_t boff = (uint32_t)((wj * 32 + nj * 8) * ST2 + k0) * 2 + laneB;
                ldsm_x2(bh[nj], sbase + OP_H + boff);
                ldsm_x2(bl[nj], sbase + OP_L + boff);
            }
#pragma unroll
            for (int mi = 0; mi < 2; mi++) {
                uint32_t aoff = (uint32_t)((wc * 32 + mi * 16) * ST2 + k0) * 2 + laneA;
                uint32_t ah[4], al[4];
                ldsm_x4(ah, sbase + OV_H + aoff);
                ldsm_x4(al, sbase + OV_L + aoff);
#pragma unroll
                for (int nj = 0; nj < 4; nj++) {
                    mma_bf16(acc[mi][nj], ah, bh[nj]);
                    mma_bf16(acc[mi][nj], ah, bl[nj]);
                    mma_bf16(acc[mi][nj], al, bh[nj]);
                }
            }
        }
        __syncthreads();
    }

    float* op = g_outpart[z];
#pragma unroll
    for (int mi = 0; mi < 2; mi++) {
        int c = wc * 32 + mi * 16 + g;
#pragma unroll
        for (int nj = 0; nj < 4; nj++) {
            int col = j0 + wj * 32 + nj * 8 + tg * 2;
            *(float2*)&op[((size_t)b * C + c) * MM + col] =
                make_float2(acc[mi][nj][0], acc[mi][nj][1]);
            *(float2*)&op[((size_t)b * C + c + 8) * MM + col] =
                make_float2(acc[mi][nj][2], acc[mi][nj][3]);
        }
    }
}

// ---------------- kernel 6: reduce split-K partials (half-batch slice) ----------------
__global__ __launch_bounds__(256) void outred_kernel(float* __restrict__ out, int b0) {
    const int i = b0 * C * MM + blockIdx.x * 256 + threadIdx.x;
    out[i] = g_outpart[0][i] + g_outpart[1][i] + g_outpart[2][i] + g_outpart[3][i];
}

// ---------------- launch: half-batch pipeline across 2 streams ----------------
extern "C" void kernel_launch(void* const* d_in, const int* in_sizes, int n_in,
                              void* d_out, int out_size) {
    const float* x  = (const float*)d_in[0];
    const float* Wq = (const float*)d_in[1];
    const float* Wk = (const float*)d_in[2];
    const float* Wv = (const float*)d_in[3];
    float* out = (float*)d_out;

    static cudaStream_t s2 = nullptr;
    static cudaEvent_t eH0 = nullptr, eC0 = nullptr;
    if (s2 == nullptr) {
        cudaStreamCreateWithFlags(&s2, cudaStreamNonBlocking);
        cudaEventCreateWithFlags(&eH0, cudaEventDisableTiming);
        cudaEventCreateWithFlags(&eC0, cudaEventDisableTiming);
    }

    cudaFuncSetAttribute(qkv_kernel, cudaFuncAttributeMaxDynamicSharedMemorySize, 96 * 1024);
    cudaFuncSetAttribute(energy_bf16_kernel, cudaFuncAttributeMaxDynamicSharedMemorySize, E_SMEM);
    cudaFuncSetAttribute(outgemm_tc_kernel, cudaFuncAttributeMaxDynamicSharedMemorySize, O_SMEM);

    const int HB = B / 2;  // half-batch = 4
    const int halfOut = HB * C * MM;

    // legacy stream: qkv (all batches) then energy half 0
    qkv_kernel<<<dim3(NN / 64, B, 3), 256, 96 * 1024>>>(x, Wq, Wk, Wv);
    energy_bf16_kernel<<<dim3(NN / 128, NN / 128, HB), 512, E_SMEM>>>(0);
    cudaEventRecord(eH0, 0);

    // stream s2: post-energy chain for half 0 (overlaps energy half 1)
    cudaStreamWaitEvent(s2, eH0, 0);
    softscan_kernel<<<dim3(NN / 16, HB), 256, 0, s2>>>(0);
    selsum_kernel<<<dim3(NN / 128, HB), 128, 0, s2>>>(0);
    topk_kernel<<<dim3(NN / 256, HB), 256, 0, s2>>>(0);
    outgemm_tc_kernel<<<dim3(MM / 64, HB, 4), 256, O_SMEM, s2>>>(0);
    outred_kernel<<<halfOut / 256, 256, 0, s2>>>(out, 0);
    cudaEventRecord(eC0, s2);

    // legacy stream: energy half 1 (concurrent with half-0 chain), then its chain
    energy_bf16_kernel<<<dim3(NN / 128, NN / 128, HB), 512, E_SMEM>>>(HB);
    softscan_kernel<<<dim3(NN / 16, HB), 256>>>(HB);
    selsum_kernel<<<dim3(NN / 128, HB), 128>>>(HB);
    topk_kernel<<<dim3(NN / 256, HB), 256>>>(HB);
    outgemm_tc_kernel<<<dim3(MM / 64, HB, 4), 256, O_SMEM>>>(HB);
    outred_kernel<<<halfOut / 256, 256>>>(out, HB);

    // join: legacy stream waits for half-0 chain before capture ends
    cudaStreamWaitEvent(0, eC0, 0);
}

// round 13
// speedup vs baseline: 1.0257x; 1.0257x over previous
#include <cuda_runtime.h>
#include <cuda_bf16.h>
#include <math.h>
#include <stdint.h>

#define B 8
#define C 128
#define NN 2048
#define MM 512

// ---------------- scratch ----------------
__device__ __nv_bfloat16 g_qh[B * NN * C];
__device__ __nv_bfloat16 g_qm[B * NN * C];
__device__ __nv_bfloat16 g_ql[B * NN * C];
__device__ __nv_bfloat16 g_kh[B * NN * C];
__device__ __nv_bfloat16 g_km[B * NN * C];
__device__ __nv_bfloat16 g_kl[B * NN * C];
__device__ __nv_bfloat16 g_vh[B * C * NN];
__device__ __nv_bfloat16 g_vl[B * C * NN];
__device__ float g_E[(size_t)B * NN * NN];
__device__ float g_rowmax[B * NN];
__device__ float g_rowsum[B * NN];
__device__ float g_selpart[B * 128 * NN];
__device__ float g_sel[B * NN];
__device__ int   g_idx[B * MM];
__device__ float g_outpart[4][B * C * MM];

__device__ __forceinline__ uint32_t smem_u32(const void* p) {
    uint32_t a;
    asm("{ .reg .u64 t; cvta.to.shared.u64 t, %1; cvt.u32.u64 %0, t; }" : "=r"(a) : "l"(p));
    return a;
}
__device__ __forceinline__ void ldsm_x4(uint32_t* r, uint32_t a) {
    asm volatile("ldmatrix.sync.aligned.m8n8.x4.shared.b16 {%0,%1,%2,%3}, [%4];"
        : "=r"(r[0]), "=r"(r[1]), "=r"(r[2]), "=r"(r[3]) : "r"(a));
}
__device__ __forceinline__ void ldsm_x2(uint32_t* r, uint32_t a) {
    asm volatile("ldmatrix.sync.aligned.m8n8.x2.shared.b16 {%0,%1}, [%2];"
        : "=r"(r[0]), "=r"(r[1]) : "r"(a));
}
__device__ __forceinline__ void mma_bf16(float* d, const uint32_t* a, const uint32_t* b) {
    asm volatile("mma.sync.aligned.m16n8k16.row.col.f32.bf16.bf16.f32 "
        "{%0,%1,%2,%3}, {%4,%5,%6,%7}, {%8,%9}, {%0,%1,%2,%3};"
        : "+f"(d[0]), "+f"(d[1]), "+f"(d[2]), "+f"(d[3])
        : "r"(a[0]), "r"(a[1]), "r"(a[2]), "r"(a[3]), "r"(b[0]), "r"(b[1]));
}

// ---------------- kernel 1: q,k,v = W @ x; q,k split h/m/l to [N][C]; v split h/l -------
__global__ __launch_bounds__(256) void qkv_kernel(const float* __restrict__ x,
                                                  const float* __restrict__ Wq,
                                                  const float* __restrict__ Wk,
                                                  const float* __restrict__ Wv) {
    extern __shared__ float sm[];
    float* Ws = sm;
    float* xs = sm + C * C;
    const int b  = blockIdx.y;
    const int n0 = blockIdx.x * 64;
    const float* W = blockIdx.z == 0 ? Wq : (blockIdx.z == 1 ? Wk : Wv);
    const int t = threadIdx.x;

    for (int i = t; i < C * C; i += 256) Ws[i] = W[i];
    const float* xb = x + (size_t)b * C * NN;
    for (int i = t; i < C * 64; i += 256) {
        int c = i >> 6, n = i & 63;
        xs[i] = xb[(size_t)c * NN + n0 + n];
    }
    __syncthreads();

    const int tx = t & 15, ty = t >> 4;
    float acc[8][4];
#pragma unroll
    for (int i = 0; i < 8; i++)
#pragma unroll
        for (int j = 0; j < 4; j++) acc[i][j] = 0.f;

    for (int c = 0; c < C; c++) {
        float4 xv = *(const float4*)&xs[c * 64 + tx * 4];
#pragma unroll
        for (int i = 0; i < 8; i++) {
            float w = Ws[(ty * 8 + i) * C + c];
            acc[i][0] = fmaf(w, xv.x, acc[i][0]);
            acc[i][1] = fmaf(w, xv.y, acc[i][1]);
            acc[i][2] = fmaf(w, xv.z, acc[i][2]);
            acc[i][3] = fmaf(w, xv.w, acc[i][3]);
        }
    }

    if (blockIdx.z == 2) {
#pragma unroll
        for (int i = 0; i < 8; i++) {
            size_t o = ((size_t)b * C + ty * 8 + i) * NN + n0 + tx * 4;
            __nv_bfloat16 h[4], l[4];
#pragma unroll
            for (int j = 0; j < 4; j++) {
                h[j] = __float2bfloat16_rn(acc[i][j]);
                l[j] = __float2bfloat16_rn(acc[i][j] - __bfloat162float(h[j]));
            }
            *(__nv_bfloat162*)&g_vh[o]     = __nv_bfloat162(h[0], h[1]);
            *(__nv_bfloat162*)&g_vh[o + 2] = __nv_bfloat162(h[2], h[3]);
            *(__nv_bfloat162*)&g_vl[o]     = __nv_bfloat162(l[0], l[1]);
            *(__nv_bfloat162*)&g_vl[o + 2] = __nv_bfloat162(l[2], l[3]);
        }
    } else {
        __nv_bfloat16* dh = blockIdx.z == 0 ? g_qh : g_kh;
        __nv_bfloat16* dm = blockIdx.z == 0 ? g_qm : g_km;
        __nv_bfloat16* dl = blockIdx.z == 0 ? g_ql : g_kl;
#pragma unroll
        for (int j = 0; j < 4; j++) {
            __nv_bfloat16 h8[8], m8[8], l8[8];
#pragma unroll
            for (int i = 0; i < 8; i++) {
                float a = acc[i][j];
                __nv_bfloat16 h = __float2bfloat16_rn(a);
                float r1 = a - __bfloat162float(h);
                __nv_bfloat16 m = __float2bfloat16_rn(r1);
                float r2 = r1 - __bfloat162float(m);
                h8[i] = h; m8[i] = m; l8[i] = __float2bfloat16_rn(r2);
            }
            size_t o = ((size_t)b * NN + n0 + tx * 4 + j) * C + ty * 8;
            *(uint4*)&dh[o] = *(uint4*)h8;
            *(uint4*)&dm[o] = *(uint4*)m8;
            *(uint4*)&dl[o] = *(uint4*)l8;
        }
    }
}

// ---------------- kernel 2: E via bf16x6 mma.sync; 512 threads ----------------
#define ST 40
#define MATB (128 * ST * 2)
#define BUFB (6 * MATB)
#define E_SMEM (2 * BUFB)

__device__ __forceinline__ void e_load_mat(uint32_t dst, const __nv_bfloat16* src, int t) {
    int r = t >> 2, k8 = t & 3;
    asm volatile("cp.async.cg.shared.global [%0], [%1], 16;"
        :: "r"(dst + (uint32_t)(r * ST + k8 * 8) * 2),
           "l"(src + (size_t)r * C + k8 * 8));
}

__global__ __launch_bounds__(512) void energy_bf16_kernel() {
    extern __shared__ char esm[];
    const uint32_t sb = smem_u32(esm);
    const int b = blockIdx.z, n0 = blockIdx.y * 128, m0 = blockIdx.x * 128;
    const int t = threadIdx.x, lane = t & 31, wid = t >> 5;
    const int wn = wid >> 2, wm = wid & 3;
    const int g = lane >> 2, tg = lane & 3;

    const __nv_bfloat16* Ah = g_qh + ((size_t)b * NN + n0) * C;
    const __nv_bfloat16* Am = g_qm + ((size_t)b * NN + n0) * C;
    const __nv_bfloat16* Al = g_ql + ((size_t)b * NN + n0) * C;
    const __nv_bfloat16* Bh = g_kh + ((size_t)b * NN + m0) * C;
    const __nv_bfloat16* Bm = g_km + ((size_t)b * NN + m0) * C;
    const __nv_bfloat16* Bl = g_kl + ((size_t)b * NN + m0) * C;

    const uint32_t laneA = (uint32_t)((lane & 15) * ST + (lane >> 4) * 8) * 2;
    const int l16 = lane & 15;
    const uint32_t laneB = (uint32_t)((l16 & 7) * ST + (l16 >> 3) * 8) * 2;

    float acc[2][4][4];
#pragma unroll
    for (int i = 0; i < 2; i++)
#pragma unroll
        for (int j = 0; j < 4; j++)
#pragma unroll
            for (int r = 0; r < 4; r++) acc[i][j][r] = 0.f;

    {
        uint32_t d0 = sb;
        e_load_mat(d0 + 0 * MATB, Ah, t);
        e_load_mat(d0 + 1 * MATB, Am, t);
        e_load_mat(d0 + 2 * MATB, Al, t);
        e_load_mat(d0 + 3 * MATB, Bh, t);
        e_load_mat(d0 + 4 * MATB, Bm, t);
        e_load_mat(d0 + 5 * MATB, Bl, t);
        asm volatile("cp.async.commit_group;" ::: "memory");
    }

    for (int ch = 0; ch < 4; ch++) {
        const int p = ch & 1;
        if (ch < 3) {
            const int c0 = (ch + 1) * 32;
            uint32_t d0 = sb + (p ^ 1) * BUFB;
            e_load_mat(d0 + 0 * MATB, Ah + c0, t);
            e_load_mat(d0 + 1 * MATB, Am + c0, t);
            e_load_mat(d0 + 2 * MATB, Al + c0, t);
            e_load_mat(d0 + 3 * MATB, Bh + c0, t);
            e_load_mat(d0 + 4 * MATB, Bm + c0, t);
            e_load_mat(d0 + 5 * MATB, Bl + c0, t);
            asm volatile("cp.async.commit_group;" ::: "memory");
            asm volatile("cp.async.wait_group 1;" ::: "memory");
        } else {
            asm volatile("cp.async.wait_group 0;" ::: "memory");
        }
        __syncthreads();

        const uint32_t base = sb + p * BUFB;
#pragma unroll
        for (int k0 = 0; k0 < 32; k0 += 16) {
            uint32_t bh[4][2], bm[4][2], bl[4][2];
#pragma unroll
            for (int j = 0; j < 4; j++) {
                uint32_t boff = (uint32_t)((wm * 32 + j * 8) * ST + k0) * 2 + laneB;
                ldsm_x2(bh[j], base + 3 * MATB + boff);
                ldsm_x2(bm[j], base + 4 * MATB + boff);
                ldsm_x2(bl[j], base + 5 * MATB + boff);
            }
#pragma unroll
            for (int i = 0; i < 2; i++) {
                uint32_t aoff = (uint32_t)((wn * 32 + i * 16) * ST + k0) * 2 + laneA;
                uint32_t ah[4], am[4], al[4];
                ldsm_x4(ah, base + 0 * MATB + aoff);
                ldsm_x4(am, base + 1 * MATB + aoff);
                ldsm_x4(al, base + 2 * MATB + aoff);
#pragma unroll
                for (int j = 0; j < 4; j++) {
                    mma_bf16(acc[i][j], ah, bh[j]);
                    mma_bf16(acc[i][j], ah, bm[j]);
                    mma_bf16(acc[i][j], am, bh[j]);
                    mma_bf16(acc[i][j], am, bm[j]);
                    mma_bf16(acc[i][j], ah, bl[j]);
                    mma_bf16(acc[i][j], al, bh[j]);
                }
            }
        }
        __syncthreads();
    }

    const float scale = 0.08838834764831845f;
    float* Eb = g_E + (size_t)b * NN * NN;
#pragma unroll
    for (int i = 0; i < 2; i++) {
        int row = n0 + wn * 32 + i * 16 + g;
#pragma unroll
        for (int j = 0; j < 4; j++) {
            int col = m0 + wm * 32 + j * 8 + tg * 2;
            *(float2*)&Eb[(size_t)row * NN + col] =
                make_float2(acc[i][j][0] * scale, acc[i][j][1] * scale);
            *(float2*)&Eb[(size_t)(row + 8) * NN + col] =
                make_float2(acc[i][j][2] * scale, acc[i][j][3] * scale);
        }
    }
}

// ---------------- kernel 3: row max/sumexp + partial col sums, row-pairs ----------------
// Per-row reduction structure/order identical to R8-R11 -> bit-identical outputs.
__global__ __launch_bounds__(256) void softscan_kernel() {
    __shared__ float redA[16], redB[16];
    const int b  = blockIdx.y;
    const int r0 = blockIdx.x * 16;
    const int t  = threadIdx.x;
    const int lane = t & 31, w = t >> 5;
    float colacc[8] = {0.f, 0.f, 0.f, 0.f, 0.f, 0.f, 0.f, 0.f};
    const float* Eb = g_E + (size_t)b * NN * NN;

    float v0[8], v1[8];
    {
        const float* Er0 = Eb + (size_t)r0 * NN;
        const float* Er1 = Eb + (size_t)(r0 + 1) * NN;
#pragma unroll
        for (int k = 0; k < 8; k++) { v0[k] = Er0[t + k * 256]; v1[k] = Er1[t + k * 256]; }
    }
    for (int rp = 0; rp < 8; rp++) {
        const int n = r0 + rp * 2;
        float w0[8], w1[8];
        if (rp < 7) {
            const float* Er0 = Eb + (size_t)(n + 2) * NN;
            const float* Er1 = Eb + (size_t)(n + 3) * NN;
#pragma unroll
            for (int k = 0; k < 8; k++) { w0[k] = Er0[t + k * 256]; w1[k] = Er1[t + k * 256]; }
        }
        float mx0 = -3.4e38f, mx1 = -3.4e38f;
#pragma unroll
        for (int k = 0; k < 8; k++) { mx0 = fmaxf(mx0, v0[k]); mx1 = fmaxf(mx1, v1[k]); }
#pragma unroll
        for (int o = 16; o; o >>= 1) {
            mx0 = fmaxf(mx0, __shfl_xor_sync(0xffffffffu, mx0, o));
            mx1 = fmaxf(mx1, __shfl_xor_sync(0xffffffffu, mx1, o));
        }
        if (lane == 0) { redA[w] = mx0; redA[8 + w] = mx1; }
        __syncthreads();
        mx0 = redA[0]; mx1 = redA[8];
#pragma unroll
        for (int i = 1; i < 8; i++) { mx0 = fmaxf(mx0, redA[i]); mx1 = fmaxf(mx1, redA[8 + i]); }

        float s0 = 0.f, s1 = 0.f;
#pragma unroll
        for (int k = 0; k < 8; k++) {
            v0[k] = __expf(v0[k] - mx0); s0 += v0[k];
            v1[k] = __expf(v1[k] - mx1); s1 += v1[k];
        }
#pragma unroll
        for (int o = 16; o; o >>= 1) {
            s0 += __shfl_xor_sync(0xffffffffu, s0, o);
            s1 += __shfl_xor_sync(0xffffffffu, s1, o);
        }
        if (lane == 0) { redB[w] = s0; redB[8 + w] = s1; }
        __syncthreads();
        s0 = redB[0]; s1 = redB[8];
#pragma unroll
        for (int i = 1; i < 8; i++) { s0 += redB[i]; s1 += redB[8 + i]; }

        if (t == 0) {
            g_rowmax[b * NN + n]     = mx0;
            g_rowsum[b * NN + n]     = s0;
            g_rowmax[b * NN + n + 1] = mx1;
            g_rowsum[b * NN + n + 1] = s1;
        }
        float i0 = 1.0f / s0, i1 = 1.0f / s1;
#pragma unroll
        for (int k = 0; k < 8; k++) colacc[k] += v0[k] * i0;
#pragma unroll
        for (int k = 0; k < 8; k++) colacc[k] += v1[k] * i1;
        if (rp < 7) {
#pragma unroll
            for (int k = 0; k < 8; k++) { v0[k] = w0[k]; v1[k] = w1[k]; }
        }
    }
    float* part = g_selpart + ((size_t)b * 128 + blockIdx.x) * NN;
#pragma unroll
    for (int k = 0; k < 8; k++) part[t + k * 256] = colacc[k];
}

// ---------------- kernel 3b: reduce partials — EXACT linear order (bit-exact contract) ---
__global__ __launch_bounds__(128) void selsum_kernel() {
    const int b = blockIdx.y;
    const int m = blockIdx.x * 128 + threadIdx.x;
    const float* p = g_selpart + (size_t)b * 128 * NN;
    float s = 0.f;
#pragma unroll 8
    for (int i = 0; i < 128; i++) s += p[(size_t)i * NN + m];
    g_sel[b * NN + m] = s;
}

// ---------------- kernel 4: stable top-k via rank counting ----------------
__global__ __launch_bounds__(256) void topk_kernel() {
    __shared__ float s[NN];
    const int b = blockIdx.y;
    for (int i = threadIdx.x; i < NN; i += 256) s[i] = g_sel[b * NN + i];
    __syncthreads();
    const int i  = blockIdx.x * 256 + threadIdx.x;
    const float vi = s[i];
    int rank = 0;
#pragma unroll 4
    for (int j = 0; j < NN; j++) {
        float vj = s[j];
        rank += (vj > vi) || (vj == vi && j < i);
    }
    if (rank < MM) g_idx[b * MM + rank] = i;
}

// ---------------- kernel 5: output GEMM via bf16x3 mma.sync, split-K=4 ----------------
#define ST2 72
#define OV_H 0
#define OV_L (128 * ST2 * 2)
#define OP_H (2 * 128 * ST2 * 2)
#define OP_L (OP_H + 64 * ST2 * 2)
#define O_SMEM (OP_L + 64 * ST2 * 2)

__global__ __launch_bounds__(256) void outgemm_tc_kernel() {
    extern __shared__ char osm[];
    __shared__ int   rows[64];
    __shared__ float rmax[64], rinv[64];
    const uint32_t sbase = smem_u32(osm);
    const int b = blockIdx.y, j0 = blockIdx.x * 64, z = blockIdx.z;
    const int t = threadIdx.x, lane = t & 31, wid = t >> 5;
    const int wc = wid & 3, wj = wid >> 2;
    const int g = lane >> 2, tg = lane & 3;

    if (t < 64) {
        int r   = g_idx[b * MM + j0 + t];
        rows[t] = r;
        rmax[t] = g_rowmax[b * NN + r];
        rinv[t] = 1.0f / g_rowsum[b * NN + r];
    }
    __syncthreads();

    const __nv_bfloat16* vh = g_vh + (size_t)b * C * NN;
    const __nv_bfloat16* vl = g_vl + (size_t)b * C * NN;
    const float* Eb = g_E + (size_t)b * NN * NN;

    const uint32_t laneA = (uint32_t)((lane & 15) * ST2 + (lane >> 4) * 8) * 2;
    const int l16 = lane & 15;
    const uint32_t laneB = (uint32_t)((l16 & 7) * ST2 + (l16 >> 3) * 8) * 2;

    float acc[2][4][4];
#pragma unroll
    for (int i = 0; i < 2; i++)
#pragma unroll
        for (int j = 0; j < 4; j++)
#pragma unroll
            for (int r = 0; r < 4; r++) acc[i][j][r] = 0.f;

    const int nBeg = z * (NN / 4);
    const int jj = t >> 2, q4 = t & 3;
    const float mxj = rmax[jj], ivj = rinv[jj];
    const size_t erow = (size_t)rows[jj] * NN;

    for (int n0 = nBeg; n0 < nBeg + NN / 4; n0 += 64) {
#pragma unroll
        for (int jld = 0; jld < 4; jld++) {
            int i = t + jld * 256;
            int c = i >> 3, k8 = i & 7;
            asm volatile("cp.async.cg.shared.global [%0], [%1], 16;"
                :: "r"(sbase + OV_H + (uint32_t)(c * ST2 + k8 * 8) * 2),
                   "l"(vh + (size_t)c * NN + n0 + k8 * 8));
            asm volatile("cp.async.cg.shared.global [%0], [%1], 16;"
                :: "r"(sbase + OV_L + (uint32_t)(c * ST2 + k8 * 8) * 2),
                   "l"(vl + (size_t)c * NN + n0 + k8 * 8));
        }
        asm volatile("cp.async.commit_group;" ::: "memory");

        {
            const float* Er = Eb + erow + n0 + q4 * 16;
#pragma unroll
            for (int i4 = 0; i4 < 4; i4++) {
                float4 e = *(const float4*)(Er + i4 * 4);
                float p0 = __expf(e.x - mxj) * ivj;
                float p1 = __expf(e.y - mxj) * ivj;
                float p2 = __expf(e.z - mxj) * ivj;
                float p3 = __expf(e.w - mxj) * ivj;
                __nv_bfloat16 h0 = __float2bfloat16_rn(p0);
                __nv_bfloat16 h1 = __float2bfloat16_rn(p1);
                __nv_bfloat16 h2 = __float2bfloat16_rn(p2);
                __nv_bfloat16 h3 = __float2bfloat16_rn(p3);
                __nv_bfloat16 l0 = __float2bfloat16_rn(p0 - __bfloat162float(h0));
                __nv_bfloat16 l1 = __float2bfloat16_rn(p1 - __bfloat162float(h1));
                __nv_bfloat16 l2 = __float2bfloat16_rn(p2 - __bfloat162float(h2));
                __nv_bfloat16 l3 = __float2bfloat16_rn(p3 - __bfloat162float(h3));
                uint32_t off = (uint32_t)(jj * ST2 + q4 * 16 + i4 * 4) * 2;
                *(__nv_bfloat162*)(osm + OP_H + off)     = __nv_bfloat162(h0, h1);
                *(__nv_bfloat162*)(osm + OP_H + off + 4) = __nv_bfloat162(h2, h3);
                *(__nv_bfloat162*)(osm + OP_L + off)     = __nv_bfloat162(l0, l1);
                *(__nv_bfloat162*)(osm + OP_L + off + 4) = __nv_bfloat162(l2, l3);
            }
        }
        asm volatile("cp.async.wait_group 0;" ::: "memory");
        __syncthreads();

#pragma unroll
        for (int k0 = 0; k0 < 64; k0 += 16) {
            uint32_t bh[4][2], bl[4][2];
#pragma unroll
            for (int nj = 0; nj < 4; nj++) {
                uint32_t boff = (uint32_t)((wj * 32 + nj * 8) * ST2 + k0) * 2 + laneB;
                ldsm_x2(bh[nj], sbase + OP_H + boff);
                ldsm_x2(bl[nj], sbase + OP_L + boff);
            }
#pragma unroll
            for (int mi = 0; mi < 2; mi++) {
                uint32_t aoff = (uint32_t)((wc * 32 + mi * 16) * ST2 + k0) * 2 + laneA;
                uint32_t ah[4], al[4];
                ldsm_x4(ah, sbase + OV_H + aoff);
                ldsm_x4(al, sbase + OV_L + aoff);
#pragma unroll
                for (int nj = 0; nj < 4; nj++) {
                    mma_bf16(acc[mi][nj], ah, bh[nj]);
                    mma_bf16(acc[mi][nj], ah, bl[nj]);
                    mma_bf16(acc[mi][nj], al, bh[nj]);
                }
            }
        }
        __syncthreads();
    }

    float* op = g_outpart[z];
#pragma unroll
    for (int mi = 0; mi < 2; mi++) {
        int c = wc * 32 + mi * 16 + g;
#pragma unroll
        for (int nj = 0; nj < 4; nj++) {
            int col = j0 + wj * 32 + nj * 8 + tg * 2;
            *(float2*)&op[((size_t)b * C + c) * MM + col] =
                make_float2(acc[mi][nj][0], acc[mi][nj][1]);
            *(float2*)&op[((size_t)b * C + c + 8) * MM + col] =
                make_float2(acc[mi][nj][2], acc[mi][nj][3]);
        }
    }
}

// ---------------- kernel 6: reduce split-K partials ----------------
__global__ __launch_bounds__(256) void outred_kernel(float* __restrict__ out) {
    const int i = blockIdx.x * 256 + threadIdx.x;
    out[i] = g_outpart[0][i] + g_outpart[1][i] + g_outpart[2][i] + g_outpart[3][i];
}

// ---------------- launch ----------------
extern "C" void kernel_launch(void* const* d_in, const int* in_sizes, int n_in,
                              void* d_out, int out_size) {
    const float* x  = (const float*)d_in[0];
    const float* Wq = (const float*)d_in[1];
    const float* Wk = (const float*)d_in[2];
    const float* Wv = (const float*)d_in[3];
    float* out = (float*)d_out;

    cudaFuncSetAttribute(qkv_kernel, cudaFuncAttributeMaxDynamicSharedMemorySize, 96 * 1024);
    cudaFuncSetAttribute(energy_bf16_kernel, cudaFuncAttributeMaxDynamicSharedMemorySize, E_SMEM);
    cudaFuncSetAttribute(outgemm_tc_kernel, cudaFuncAttributeMaxDynamicSharedMemorySize, O_SMEM);

    qkv_kernel<<<dim3(NN / 64, B, 3), 256, 96 * 1024>>>(x, Wq, Wk, Wv);
    energy_bf16_kernel<<<dim3(NN / 128, NN / 128, B), 512, E_SMEM>>>();
    softscan_kernel<<<dim3(NN / 16, B), 256>>>();
    selsum_kernel<<<dim3(NN / 128, B), 128>>>();
    topk_kernel<<<dim3(NN / 256, B), 256>>>();
    outgemm_tc_kernel<<<dim3(MM / 64, B, 4), 256, O_SMEM>>>();
    outred_kernel<<<(B * C * MM) / 256, 256>>>(out);
}

// round 14
// speedup vs baseline: 1.0328x; 1.0070x over previous
#include <cuda_runtime.h>
#include <cuda_bf16.h>
#include <math.h>
#include <stdint.h>

#define B 8
#define C 128
#define NN 2048
#define MM 512

// ---------------- scratch ----------------
__device__ __nv_bfloat16 g_qh[B * NN * C];
__device__ __nv_bfloat16 g_qm[B * NN * C];
__device__ __nv_bfloat16 g_ql[B * NN * C];
__device__ __nv_bfloat16 g_kh[B * NN * C];
__device__ __nv_bfloat16 g_km[B * NN * C];
__device__ __nv_bfloat16 g_kl[B * NN * C];
__device__ __nv_bfloat16 g_vh[B * C * NN];
__device__ __nv_bfloat16 g_vl[B * C * NN];
__device__ float g_E[(size_t)B * NN * NN];
__device__ float g_rowmax[B * NN];
__device__ float g_rowsum[B * NN];
__device__ float g_selpart[B * 128 * NN];
__device__ float g_sel[B * NN];
__device__ int   g_idx[B * MM];
__device__ float g_outpart[4][B * C * MM];

__device__ __forceinline__ uint32_t smem_u32(const void* p) {
    uint32_t a;
    asm("{ .reg .u64 t; cvta.to.shared.u64 t, %1; cvt.u32.u64 %0, t; }" : "=r"(a) : "l"(p));
    return a;
}
__device__ __forceinline__ void ldsm_x4(uint32_t* r, uint32_t a) {
    asm volatile("ldmatrix.sync.aligned.m8n8.x4.shared.b16 {%0,%1,%2,%3}, [%4];"
        : "=r"(r[0]), "=r"(r[1]), "=r"(r[2]), "=r"(r[3]) : "r"(a));
}
__device__ __forceinline__ void ldsm_x2(uint32_t* r, uint32_t a) {
    asm volatile("ldmatrix.sync.aligned.m8n8.x2.shared.b16 {%0,%1}, [%2];"
        : "=r"(r[0]), "=r"(r[1]) : "r"(a));
}
__device__ __forceinline__ void mma_bf16(float* d, const uint32_t* a, const uint32_t* b) {
    asm volatile("mma.sync.aligned.m16n8k16.row.col.f32.bf16.bf16.f32 "
        "{%0,%1,%2,%3}, {%4,%5,%6,%7}, {%8,%9}, {%0,%1,%2,%3};"
        : "+f"(d[0]), "+f"(d[1]), "+f"(d[2]), "+f"(d[3])
        : "r"(a[0]), "r"(a[1]), "r"(a[2]), "r"(a[3]), "r"(b[0]), "r"(b[1]));
}

// ---------------- kernel 1: q,k,v = W @ x; q,k split h/m/l to [N][C]; v split h/l -------
__global__ __launch_bounds__(256) void qkv_kernel(const float* __restrict__ x,
                                                  const float* __restrict__ Wq,
                                                  const float* __restrict__ Wk,
                                                  const float* __restrict__ Wv) {
    extern __shared__ float sm[];
    float* Ws = sm;
    float* xs = sm + C * C;
    const int b  = blockIdx.y;
    const int n0 = blockIdx.x * 64;
    const float* W = blockIdx.z == 0 ? Wq : (blockIdx.z == 1 ? Wk : Wv);
    const int t = threadIdx.x;

    for (int i = t; i < C * C; i += 256) Ws[i] = W[i];
    const float* xb = x + (size_t)b * C * NN;
    for (int i = t; i < C * 64; i += 256) {
        int c = i >> 6, n = i & 63;
        xs[i] = xb[(size_t)c * NN + n0 + n];
    }
    __syncthreads();

    const int tx = t & 15, ty = t >> 4;
    float acc[8][4];
#pragma unroll
    for (int i = 0; i < 8; i++)
#pragma unroll
        for (int j = 0; j < 4; j++) acc[i][j] = 0.f;

    for (int c = 0; c < C; c++) {
        float4 xv = *(const float4*)&xs[c * 64 + tx * 4];
#pragma unroll
        for (int i = 0; i < 8; i++) {
            float w = Ws[(ty * 8 + i) * C + c];
            acc[i][0] = fmaf(w, xv.x, acc[i][0]);
            acc[i][1] = fmaf(w, xv.y, acc[i][1]);
            acc[i][2] = fmaf(w, xv.z, acc[i][2]);
            acc[i][3] = fmaf(w, xv.w, acc[i][3]);
        }
    }

    if (blockIdx.z == 2) {
#pragma unroll
        for (int i = 0; i < 8; i++) {
            size_t o = ((size_t)b * C + ty * 8 + i) * NN + n0 + tx * 4;
            __nv_bfloat16 h[4], l[4];
#pragma unroll
            for (int j = 0; j < 4; j++) {
                h[j] = __float2bfloat16_rn(acc[i][j]);
                l[j] = __float2bfloat16_rn(acc[i][j] - __bfloat162float(h[j]));
            }
            *(__nv_bfloat162*)&g_vh[o]     = __nv_bfloat162(h[0], h[1]);
            *(__nv_bfloat162*)&g_vh[o + 2] = __nv_bfloat162(h[2], h[3]);
            *(__nv_bfloat162*)&g_vl[o]     = __nv_bfloat162(l[0], l[1]);
            *(__nv_bfloat162*)&g_vl[o + 2] = __nv_bfloat162(l[2], l[3]);
        }
    } else {
        __nv_bfloat16* dh = blockIdx.z == 0 ? g_qh : g_kh;
        __nv_bfloat16* dm = blockIdx.z == 0 ? g_qm : g_km;
        __nv_bfloat16* dl = blockIdx.z == 0 ? g_ql : g_kl;
#pragma unroll
        for (int j = 0; j < 4; j++) {
            __nv_bfloat16 h8[8], m8[8], l8[8];
#pragma unroll
            for (int i = 0; i < 8; i++) {
                float a = acc[i][j];
                __nv_bfloat16 h = __float2bfloat16_rn(a);
                float r1 = a - __bfloat162float(h);
                __nv_bfloat16 m = __float2bfloat16_rn(r1);
                float r2 = r1 - __bfloat162float(m);
                h8[i] = h; m8[i] = m; l8[i] = __float2bfloat16_rn(r2);
            }
            size_t o = ((size_t)b * NN + n0 + tx * 4 + j) * C + ty * 8;
            *(uint4*)&dh[o] = *(uint4*)h8;
            *(uint4*)&dm[o] = *(uint4*)m8;
            *(uint4*)&dl[o] = *(uint4*)l8;
        }
    }
}

// ---------------- kernel 2: E via bf16x6 mma.sync; 512 threads ----------------
#define ST 40
#define MATB (128 * ST * 2)
#define BUFB (6 * MATB)
#define E_SMEM (2 * BUFB)

__device__ __forceinline__ void e_load_mat(uint32_t dst, const __nv_bfloat16* src, int t) {
    int r = t >> 2, k8 = t & 3;
    asm volatile("cp.async.cg.shared.global [%0], [%1], 16;"
        :: "r"(dst + (uint32_t)(r * ST + k8 * 8) * 2),
           "l"(src + (size_t)r * C + k8 * 8));
}

__global__ __launch_bounds__(512) void energy_bf16_kernel() {
    extern __shared__ char esm[];
    const uint32_t sb = smem_u32(esm);
    const int b = blockIdx.z, n0 = blockIdx.y * 128, m0 = blockIdx.x * 128;
    const int t = threadIdx.x, lane = t & 31, wid = t >> 5;
    const int wn = wid >> 2, wm = wid & 3;
    const int g = lane >> 2, tg = lane & 3;

    const __nv_bfloat16* Ah = g_qh + ((size_t)b * NN + n0) * C;
    const __nv_bfloat16* Am = g_qm + ((size_t)b * NN + n0) * C;
    const __nv_bfloat16* Al = g_ql + ((size_t)b * NN + n0) * C;
    const __nv_bfloat16* Bh = g_kh + ((size_t)b * NN + m0) * C;
    const __nv_bfloat16* Bm = g_km + ((size_t)b * NN + m0) * C;
    const __nv_bfloat16* Bl = g_kl + ((size_t)b * NN + m0) * C;

    const uint32_t laneA = (uint32_t)((lane & 15) * ST + (lane >> 4) * 8) * 2;
    const int l16 = lane & 15;
    const uint32_t laneB = (uint32_t)((l16 & 7) * ST + (l16 >> 3) * 8) * 2;

    float acc[2][4][4];
#pragma unroll
    for (int i = 0; i < 2; i++)
#pragma unroll
        for (int j = 0; j < 4; j++)
#pragma unroll
            for (int r = 0; r < 4; r++) acc[i][j][r] = 0.f;

    {
        uint32_t d0 = sb;
        e_load_mat(d0 + 0 * MATB, Ah, t);
        e_load_mat(d0 + 1 * MATB, Am, t);
        e_load_mat(d0 + 2 * MATB, Al, t);
        e_load_mat(d0 + 3 * MATB, Bh, t);
        e_load_mat(d0 + 4 * MATB, Bm, t);
        e_load_mat(d0 + 5 * MATB, Bl, t);
        asm volatile("cp.async.commit_group;" ::: "memory");
    }

    for (int ch = 0; ch < 4; ch++) {
        const int p = ch & 1;
        if (ch < 3) {
            const int c0 = (ch + 1) * 32;
            uint32_t d0 = sb + (p ^ 1) * BUFB;
            e_load_mat(d0 + 0 * MATB, Ah + c0, t);
            e_load_mat(d0 + 1 * MATB, Am + c0, t);
            e_load_mat(d0 + 2 * MATB, Al + c0, t);
            e_load_mat(d0 + 3 * MATB, Bh + c0, t);
            e_load_mat(d0 + 4 * MATB, Bm + c0, t);
            e_load_mat(d0 + 5 * MATB, Bl + c0, t);
            asm volatile("cp.async.commit_group;" ::: "memory");
            asm volatile("cp.async.wait_group 1;" ::: "memory");
        } else {
            asm volatile("cp.async.wait_group 0;" ::: "memory");
        }
        __syncthreads();

        const uint32_t base = sb + p * BUFB;
#pragma unroll
        for (int k0 = 0; k0 < 32; k0 += 16) {
            uint32_t bh[4][2], bm[4][2], bl[4][2];
#pragma unroll
            for (int j = 0; j < 4; j++) {
                uint32_t boff = (uint32_t)((wm * 32 + j * 8) * ST + k0) * 2 + laneB;
                ldsm_x2(bh[j], base + 3 * MATB + boff);
                ldsm_x2(bm[j], base + 4 * MATB + boff);
                ldsm_x2(bl[j], base + 5 * MATB + boff);
            }
#pragma unroll
            for (int i = 0; i < 2; i++) {
                uint32_t aoff = (uint32_t)((wn * 32 + i * 16) * ST + k0) * 2 + laneA;
                uint32_t ah[4], am[4], al[4];
                ldsm_x4(ah, base + 0 * MATB + aoff);
                ldsm_x4(am, base + 1 * MATB + aoff);
                ldsm_x4(al, base + 2 * MATB + aoff);
#pragma unroll
                for (int j = 0; j < 4; j++) {
                    mma_bf16(acc[i][j], ah, bh[j]);
                    mma_bf16(acc[i][j], ah, bm[j]);
                    mma_bf16(acc[i][j], am, bh[j]);
                    mma_bf16(acc[i][j], am, bm[j]);
                    mma_bf16(acc[i][j], ah, bl[j]);
                    mma_bf16(acc[i][j], al, bh[j]);
                }
            }
        }
        __syncthreads();
    }

    const float scale = 0.08838834764831845f;
    float* Eb = g_E + (size_t)b * NN * NN;
#pragma unroll
    for (int i = 0; i < 2; i++) {
        int row = n0 + wn * 32 + i * 16 + g;
#pragma unroll
        for (int j = 0; j < 4; j++) {
            int col = m0 + wm * 32 + j * 8 + tg * 2;
            *(float2*)&Eb[(size_t)row * NN + col] =
                make_float2(acc[i][j][0] * scale, acc[i][j][1] * scale);
            *(float2*)&Eb[(size_t)(row + 8) * NN + col] =
                make_float2(acc[i][j][2] * scale, acc[i][j][3] * scale);
        }
    }
}

// ---------------- kernel 3: row max/sumexp + partial col sums, row-pairs ----------------
__global__ __launch_bounds__(256) void softscan_kernel() {
    __shared__ float redA[16], redB[16];
    const int b  = blockIdx.y;
    const int r0 = blockIdx.x * 16;
    const int t  = threadIdx.x;
    const int lane = t & 31, w = t >> 5;
    float colacc[8] = {0.f, 0.f, 0.f, 0.f, 0.f, 0.f, 0.f, 0.f};
    const float* Eb = g_E + (size_t)b * NN * NN;

    float v0[8], v1[8];
    {
        const float* Er0 = Eb + (size_t)r0 * NN;
        const float* Er1 = Eb + (size_t)(r0 + 1) * NN;
#pragma unroll
        for (int k = 0; k < 8; k++) { v0[k] = Er0[t + k * 256]; v1[k] = Er1[t + k * 256]; }
    }
    for (int rp = 0; rp < 8; rp++) {
        const int n = r0 + rp * 2;
        float w0[8], w1[8];
        if (rp < 7) {
            const float* Er0 = Eb + (size_t)(n + 2) * NN;
            const float* Er1 = Eb + (size_t)(n + 3) * NN;
#pragma unroll
            for (int k = 0; k < 8; k++) { w0[k] = Er0[t + k * 256]; w1[k] = Er1[t + k * 256]; }
        }
        float mx0 = -3.4e38f, mx1 = -3.4e38f;
#pragma unroll
        for (int k = 0; k < 8; k++) { mx0 = fmaxf(mx0, v0[k]); mx1 = fmaxf(mx1, v1[k]); }
#pragma unroll
        for (int o = 16; o; o >>= 1) {
            mx0 = fmaxf(mx0, __shfl_xor_sync(0xffffffffu, mx0, o));
            mx1 = fmaxf(mx1, __shfl_xor_sync(0xffffffffu, mx1, o));
        }
        if (lane == 0) { redA[w] = mx0; redA[8 + w] = mx1; }
        __syncthreads();
        mx0 = redA[0]; mx1 = redA[8];
#pragma unroll
        for (int i = 1; i < 8; i++) { mx0 = fmaxf(mx0, redA[i]); mx1 = fmaxf(mx1, redA[8 + i]); }

        float s0 = 0.f, s1 = 0.f;
#pragma unroll
        for (int k = 0; k < 8; k++) {
            v0[k] = __expf(v0[k] - mx0); s0 += v0[k];
            v1[k] = __expf(v1[k] - mx1); s1 += v1[k];
        }
#pragma unroll
        for (int o = 16; o; o >>= 1) {
            s0 += __shfl_xor_sync(0xffffffffu, s0, o);
            s1 += __shfl_xor_sync(0xffffffffu, s1, o);
        }
        if (lane == 0) { redB[w] = s0; redB[8 + w] = s1; }
        __syncthreads();
        s0 = redB[0]; s1 = redB[8];
#pragma unroll
        for (int i = 1; i < 8; i++) { s0 += redB[i]; s1 += redB[8 + i]; }

        if (t == 0) {
            g_rowmax[b * NN + n]     = mx0;
            g_rowsum[b * NN + n]     = s0;
            g_rowmax[b * NN + n + 1] = mx1;
            g_rowsum[b * NN + n + 1] = s1;
        }
        float i0 = 1.0f / s0, i1 = 1.0f / s1;
#pragma unroll
        for (int k = 0; k < 8; k++) colacc[k] += v0[k] * i0;
#pragma unroll
        for (int k = 0; k < 8; k++) colacc[k] += v1[k] * i1;
        if (rp < 7) {
#pragma unroll
            for (int k = 0; k < 8; k++) { v0[k] = w0[k]; v1[k] = w1[k]; }
        }
    }
    float* part = g_selpart + ((size_t)b * 128 + blockIdx.x) * NN;
#pragma unroll
    for (int k = 0; k < 8; k++) part[t + k * 256] = colacc[k];
}

// ---------------- kernel 3b: reduce partials — exact linear order, explicit MLP=16 ------
__global__ __launch_bounds__(128) void selsum_kernel() {
    const int b = blockIdx.y;
    const int m = blockIdx.x * 128 + threadIdx.x;
    const float* p = g_selpart + (size_t)b * 128 * NN + m;
    float s = 0.f;
    for (int i0 = 0; i0 < 128; i0 += 16) {
        float v[16];
#pragma unroll
        for (int j = 0; j < 16; j++) v[j] = p[(size_t)(i0 + j) * NN];
#pragma unroll
        for (int j = 0; j < 16; j++) s += v[j];   // same linear order -> bit-identical
    }
    g_sel[b * NN + m] = s;
}

// ---------------- kernel 4: stable top-k via rank counting ----------------
__global__ __launch_bounds__(256) void topk_kernel() {
    __shared__ float s[NN];
    const int b = blockIdx.y;
    for (int i = threadIdx.x; i < NN; i += 256) s[i] = g_sel[b * NN + i];
    __syncthreads();
    const int i  = blockIdx.x * 256 + threadIdx.x;
    const float vi = s[i];
    int rank = 0;
#pragma unroll 4
    for (int j = 0; j < NN; j++) {
        float vj = s[j];
        rank += (vj > vi) || (vj == vi && j < i);
    }
    if (rank < MM) g_idx[b * MM + rank] = i;
}

// ---------------- kernel 5: output GEMM via bf16x3 mma.sync, split-K=4 ----------------
#define ST2 72
#define OV_H 0
#define OV_L (128 * ST2 * 2)
#define OP_H (2 * 128 * ST2 * 2)
#define OP_L (OP_H + 64 * ST2 * 2)
#define O_SMEM (OP_L + 64 * ST2 * 2)

__global__ __launch_bounds__(256) void outgemm_tc_kernel() {
    extern __shared__ char osm[];
    __shared__ int   rows[64];
    __shared__ float rmax[64], rinv[64];
    const uint32_t sbase = smem_u32(osm);
    const int b = blockIdx.y, j0 = blockIdx.x * 64, z = blockIdx.z;
    const int t = threadIdx.x, lane = t & 31, wid = t >> 5;
    const int wc = wid & 3, wj = wid >> 2;
    const int g = lane >> 2, tg = lane & 3;

    if (t < 64) {
        int r   = g_idx[b * MM + j0 + t];
        rows[t] = r;
        rmax[t] = g_rowmax[b * NN + r];
        rinv[t] = 1.0f / g_rowsum[b * NN + r];
    }
    __syncthreads();

    const __nv_bfloat16* vh = g_vh + (size_t)b * C * NN;
    const __nv_bfloat16* vl = g_vl + (size_t)b * C * NN;
    const float* Eb = g_E + (size_t)b * NN * NN;

    const uint32_t laneA = (uint32_t)((lane & 15) * ST2 + (lane >> 4) * 8) * 2;
    const int l16 = lane & 15;
    const uint32_t laneB = (uint32_t)((l16 & 7) * ST2 + (l16 >> 3) * 8) * 2;

    float acc[2][4][4];
#pragma unroll
    for (int i = 0; i < 2; i++)
#pragma unroll
        for (int j = 0; j < 4; j++)
#pragma unroll
            for (int r = 0; r < 4; r++) acc[i][j][r] = 0.f;

    const int nBeg = z * (NN / 4);
    const int jj = t >> 2, q4 = t & 3;
    const float mxj = rmax[jj], ivj = rinv[jj];
    const size_t erow = (size_t)rows[jj] * NN;

    for (int n0 = nBeg; n0 < nBeg + NN / 4; n0 += 64) {
#pragma unroll
        for (int jld = 0; jld < 4; jld++) {
            int i = t + jld * 256;
            int c = i >> 3, k8 = i & 7;
            asm volatile("cp.async.cg.shared.global [%0], [%1], 16;"
                :: "r"(sbase + OV_H + (uint32_t)(c * ST2 + k8 * 8) * 2),
                   "l"(vh + (size_t)c * NN + n0 + k8 * 8));
            asm volatile("cp.async.cg.shared.global [%0], [%1], 16;"
                :: "r"(sbase + OV_L + (uint32_t)(c * ST2 + k8 * 8) * 2),
                   "l"(vl + (size_t)c * NN + n0 + k8 * 8));
        }
        asm volatile("cp.async.commit_group;" ::: "memory");

        {
            const float* Er = Eb + erow + n0 + q4 * 16;
#pragma unroll
            for (int i4 = 0; i4 < 4; i4++) {
                float4 e = *(const float4*)(Er + i4 * 4);
                float p0 = __expf(e.x - mxj) * ivj;
                float p1 = __expf(e.y - mxj) * ivj;
                float p2 = __expf(e.z - mxj) * ivj;
                float p3 = __expf(e.w - mxj) * ivj;
                __nv_bfloat16 h0 = __float2bfloat16_rn(p0);
                __nv_bfloat16 h1 = __float2bfloat16_rn(p1);
                __nv_bfloat16 h2 = __float2bfloat16_rn(p2);
                __nv_bfloat16 h3 = __float2bfloat16_rn(p3);
                __nv_bfloat16 l0 = __float2bfloat16_rn(p0 - __bfloat162float(h0));
                __nv_bfloat16 l1 = __float2bfloat16_rn(p1 - __bfloat162float(h1));
                __nv_bfloat16 l2 = __float2bfloat16_rn(p2 - __bfloat162float(h2));
                __nv_bfloat16 l3 = __float2bfloat16_rn(p3 - __bfloat162float(h3));
                uint32_t off = (uint32_t)(jj * ST2 + q4 * 16 + i4 * 4) * 2;
                *(__nv_bfloat162*)(osm + OP_H + off)     = __nv_bfloat162(h0, h1);
                *(__nv_bfloat162*)(osm + OP_H + off + 4) = __nv_bfloat162(h2, h3);
                *(__nv_bfloat162*)(osm + OP_L + off)     = __nv_bfloat162(l0, l1);
                *(__nv_bfloat162*)(osm + OP_L + off + 4) = __nv_bfloat162(l2, l3);
            }
        }
        asm volatile("cp.async.wait_group 0;" ::: "memory");
        __syncthreads();

#pragma unroll
        for (int k0 = 0; k0 < 64; k0 += 16) {
            uint32_t bh[4][2], bl[4][2];
#pragma unroll
            for (int nj = 0; nj < 4; nj++) {
                uint32_t boff = (uint32_t)((wj * 32 + nj * 8) * ST2 + k0) * 2 + laneB;
                ldsm_x2(bh[nj], sbase + OP_H + boff);
                ldsm_x2(bl[nj], sbase + OP_L + boff);
            }
#pragma unroll
            for (int mi = 0; mi < 2; mi++) {
                uint32_t aoff = (uint32_t)((wc * 32 + mi * 16) * ST2 + k0) * 2 + laneA;
                uint32_t ah[4], al[4];
                ldsm_x4(ah, sbase + OV_H + aoff);
                ldsm_x4(al, sbase + OV_L + aoff);
#pragma unroll
                for (int nj = 0; nj < 4; nj++) {
                    mma_bf16(acc[mi][nj], ah, bh[nj]);
                    mma_bf16(acc[mi][nj], ah, bl[nj]);
                    mma_bf16(acc[mi][nj], al, bh[nj]);
                }
            }
        }
        __syncthreads();
    }

    float* op = g_outpart[z];
#pragma unroll
    for (int mi = 0; mi < 2; mi++) {
        int c = wc * 32 + mi * 16 + g;
#pragma unroll
        for (int nj = 0; nj < 4; nj++) {
            int col = j0 + wj * 32 + nj * 8 + tg * 2;
            *(float2*)&op[((size_t)b * C + c) * MM + col] =
                make_float2(acc[mi][nj][0], acc[mi][nj][1]);
            *(float2*)&op[((size_t)b * C + c + 8) * MM + col] =
                make_float2(acc[mi][nj][2], acc[mi][nj][3]);
        }
    }
}

// ---------------- kernel 6: reduce split-K partials ----------------
__global__ __launch_bounds__(256) void outred_kernel(float* __restrict__ out) {
    const int i = blockIdx.x * 256 + threadIdx.x;
    out[i] = g_outpart[0][i] + g_outpart[1][i] + g_outpart[2][i] + g_outpart[3][i];
}

// ---------------- launch ----------------
extern "C" void kernel_launch(void* const* d_in, const int* in_sizes, int n_in,
                              void* d_out, int out_size) {
    const float* x  = (const float*)d_in[0];
    const float* Wq = (const float*)d_in[1];
    const float* Wk = (const float*)d_in[2];
    const float* Wv = (const float*)d_in[3];
    float* out = (float*)d_out;

    cudaFuncSetAttribute(qkv_kernel, cudaFuncAttributeMaxDynamicSharedMemorySize, 96 * 1024);
    cudaFuncSetAttribute(energy_bf16_kernel, cudaFuncAttributeMaxDynamicSharedMemorySize, E_SMEM);
    cudaFuncSetAttribute(outgemm_tc_kernel, cudaFuncAttributeMaxDynamicSharedMemorySize, O_SMEM);

    qkv_kernel<<<dim3(NN / 64, B, 3), 256, 96 * 1024>>>(x, Wq, Wk, Wv);
    energy_bf16_kernel<<<dim3(NN / 128, NN / 128, B), 512, E_SMEM>>>();
    softscan_kernel<<<dim3(NN / 16, B), 256>>>();
    selsum_kernel<<<dim3(NN / 128, B), 128>>>();
    topk_kernel<<<dim3(NN / 256, B), 256>>>();
    outgemm_tc_kernel<<<dim3(MM / 64, B, 4), 256, O_SMEM>>>();
    outred_kernel<<<(B * C * MM) / 256, 256>>>(out);
}

// round 15
// speedup vs baseline: 1.0344x; 1.0015x over previous
#include <cuda_runtime.h>
#include <cuda_bf16.h>
#include <math.h>
#include <stdint.h>

#define B 8
#define C 128
#define NN 2048
#define MM 512

// ---------------- scratch ----------------
__device__ __nv_bfloat16 g_qh[B * NN * C];
__device__ __nv_bfloat16 g_qm[B * NN * C];
__device__ __nv_bfloat16 g_ql[B * NN * C];
__device__ __nv_bfloat16 g_kh[B * NN * C];
__device__ __nv_bfloat16 g_km[B * NN * C];
__device__ __nv_bfloat16 g_kl[B * NN * C];
__device__ __nv_bfloat16 g_vh[B * C * NN];
__device__ __nv_bfloat16 g_vl[B * C * NN];
__device__ float g_E[(size_t)B * NN * NN];
__device__ float g_rowmax[B * NN];
__device__ float g_rowsum[B * NN];
__device__ float g_selpart[B * 128 * NN];
__device__ float g_sel[B * NN];
__device__ int   g_idx[B * MM];
__device__ float g_outpart[4][B * C * MM];

__device__ __forceinline__ uint32_t smem_u32(const void* p) {
    uint32_t a;
    asm("{ .reg .u64 t; cvta.to.shared.u64 t, %1; cvt.u32.u64 %0, t; }" : "=r"(a) : "l"(p));
    return a;
}
__device__ __forceinline__ void ldsm_x4(uint32_t* r, uint32_t a) {
    asm volatile("ldmatrix.sync.aligned.m8n8.x4.shared.b16 {%0,%1,%2,%3}, [%4];"
        : "=r"(r[0]), "=r"(r[1]), "=r"(r[2]), "=r"(r[3]) : "r"(a));
}
__device__ __forceinline__ void ldsm_x2(uint32_t* r, uint32_t a) {
    asm volatile("ldmatrix.sync.aligned.m8n8.x2.shared.b16 {%0,%1}, [%2];"
        : "=r"(r[0]), "=r"(r[1]) : "r"(a));
}
__device__ __forceinline__ void mma_bf16(float* d, const uint32_t* a, const uint32_t* b) {
    asm volatile("mma.sync.aligned.m16n8k16.row.col.f32.bf16.bf16.f32 "
        "{%0,%1,%2,%3}, {%4,%5,%6,%7}, {%8,%9}, {%0,%1,%2,%3};"
        : "+f"(d[0]), "+f"(d[1]), "+f"(d[2]), "+f"(d[3])
        : "r"(a[0]), "r"(a[1]), "r"(a[2]), "r"(a[3]), "r"(b[0]), "r"(b[1]));
}

// ---------------- kernel 1: q,k,v = W @ x; q,k split h/m/l to [N][C]; v split h/l -------
__global__ __launch_bounds__(256) void qkv_kernel(const float* __restrict__ x,
                                                  const float* __restrict__ Wq,
                                                  const float* __restrict__ Wk,
                                                  const float* __restrict__ Wv) {
    extern __shared__ float sm[];
    float* Ws = sm;
    float* xs = sm + C * C;
    const int b  = blockIdx.y;
    const int n0 = blockIdx.x * 64;
    const float* W = blockIdx.z == 0 ? Wq : (blockIdx.z == 1 ? Wk : Wv);
    const int t = threadIdx.x;

    for (int i = t; i < C * C; i += 256) Ws[i] = W[i];
    const float* xb = x + (size_t)b * C * NN;
    for (int i = t; i < C * 64; i += 256) {
        int c = i >> 6, n = i & 63;
        xs[i] = xb[(size_t)c * NN + n0 + n];
    }
    __syncthreads();

    const int tx = t & 15, ty = t >> 4;
    float acc[8][4];
#pragma unroll
    for (int i = 0; i < 8; i++)
#pragma unroll
        for (int j = 0; j < 4; j++) acc[i][j] = 0.f;

    for (int c = 0; c < C; c++) {
        float4 xv = *(const float4*)&xs[c * 64 + tx * 4];
#pragma unroll
        for (int i = 0; i < 8; i++) {
            float w = Ws[(ty * 8 + i) * C + c];
            acc[i][0] = fmaf(w, xv.x, acc[i][0]);
            acc[i][1] = fmaf(w, xv.y, acc[i][1]);
            acc[i][2] = fmaf(w, xv.z, acc[i][2]);
            acc[i][3] = fmaf(w, xv.w, acc[i][3]);
        }
    }

    if (blockIdx.z == 2) {
#pragma unroll
        for (int i = 0; i < 8; i++) {
            size_t o = ((size_t)b * C + ty * 8 + i) * NN + n0 + tx * 4;
            __nv_bfloat16 h[4], l[4];
#pragma unroll
            for (int j = 0; j < 4; j++) {
                h[j] = __float2bfloat16_rn(acc[i][j]);
                l[j] = __float2bfloat16_rn(acc[i][j] - __bfloat162float(h[j]));
            }
            *(__nv_bfloat162*)&g_vh[o]     = __nv_bfloat162(h[0], h[1]);
            *(__nv_bfloat162*)&g_vh[o + 2] = __nv_bfloat162(h[2], h[3]);
            *(__nv_bfloat162*)&g_vl[o]     = __nv_bfloat162(l[0], l[1]);
            *(__nv_bfloat162*)&g_vl[o + 2] = __nv_bfloat162(l[2], l[3]);
        }
    } else {
        __nv_bfloat16* dh = blockIdx.z == 0 ? g_qh : g_kh;
        __nv_bfloat16* dm = blockIdx.z == 0 ? g_qm : g_km;
        __nv_bfloat16* dl = blockIdx.z == 0 ? g_ql : g_kl;
#pragma unroll
        for (int j = 0; j < 4; j++) {
            __nv_bfloat16 h8[8], m8[8], l8[8];
#pragma unroll
            for (int i = 0; i < 8; i++) {
                float a = acc[i][j];
                __nv_bfloat16 h = __float2bfloat16_rn(a);
                float r1 = a - __bfloat162float(h);
                __nv_bfloat16 m = __float2bfloat16_rn(r1);
                float r2 = r1 - __bfloat162float(m);
                h8[i] = h; m8[i] = m; l8[i] = __float2bfloat16_rn(r2);
            }
            size_t o = ((size_t)b * NN + n0 + tx * 4 + j) * C + ty * 8;
            *(uint4*)&dh[o] = *(uint4*)h8;
            *(uint4*)&dm[o] = *(uint4*)m8;
            *(uint4*)&dl[o] = *(uint4*)l8;
        }
    }
}

// ---------------- kernel 2: E via bf16x6 mma.sync; 512 threads ----------------
#define ST 40
#define MATB (128 * ST * 2)
#define BUFB (6 * MATB)
#define E_SMEM (2 * BUFB)

__device__ __forceinline__ void e_load_mat(uint32_t dst, const __nv_bfloat16* src, int t) {
    int r = t >> 2, k8 = t & 3;
    asm volatile("cp.async.cg.shared.global [%0], [%1], 16;"
        :: "r"(dst + (uint32_t)(r * ST + k8 * 8) * 2),
           "l"(src + (size_t)r * C + k8 * 8));
}

__global__ __launch_bounds__(512) void energy_bf16_kernel() {
    extern __shared__ char esm[];
    const uint32_t sb = smem_u32(esm);
    const int b = blockIdx.z, n0 = blockIdx.y * 128, m0 = blockIdx.x * 128;
    const int t = threadIdx.x, lane = t & 31, wid = t >> 5;
    const int wn = wid >> 2, wm = wid & 3;
    const int g = lane >> 2, tg = lane & 3;

    const __nv_bfloat16* Ah = g_qh + ((size_t)b * NN + n0) * C;
    const __nv_bfloat16* Am = g_qm + ((size_t)b * NN + n0) * C;
    const __nv_bfloat16* Al = g_ql + ((size_t)b * NN + n0) * C;
    const __nv_bfloat16* Bh = g_kh + ((size_t)b * NN + m0) * C;
    const __nv_bfloat16* Bm = g_km + ((size_t)b * NN + m0) * C;
    const __nv_bfloat16* Bl = g_kl + ((size_t)b * NN + m0) * C;

    const uint32_t laneA = (uint32_t)((lane & 15) * ST + (lane >> 4) * 8) * 2;
    const int l16 = lane & 15;
    const uint32_t laneB = (uint32_t)((l16 & 7) * ST + (l16 >> 3) * 8) * 2;

    float acc[2][4][4];
#pragma unroll
    for (int i = 0; i < 2; i++)
#pragma unroll
        for (int j = 0; j < 4; j++)
#pragma unroll
            for (int r = 0; r < 4; r++) acc[i][j][r] = 0.f;

    {
        uint32_t d0 = sb;
        e_load_mat(d0 + 0 * MATB, Ah, t);
        e_load_mat(d0 + 1 * MATB, Am, t);
        e_load_mat(d0 + 2 * MATB, Al, t);
        e_load_mat(d0 + 3 * MATB, Bh, t);
        e_load_mat(d0 + 4 * MATB, Bm, t);
        e_load_mat(d0 + 5 * MATB, Bl, t);
        asm volatile("cp.async.commit_group;" ::: "memory");
    }

    for (int ch = 0; ch < 4; ch++) {
        const int p = ch & 1;
        if (ch < 3) {
            const int c0 = (ch + 1) * 32;
            uint32_t d0 = sb + (p ^ 1) * BUFB;
            e_load_mat(d0 + 0 * MATB, Ah + c0, t);
            e_load_mat(d0 + 1 * MATB, Am + c0, t);
            e_load_mat(d0 + 2 * MATB, Al + c0, t);
            e_load_mat(d0 + 3 * MATB, Bh + c0, t);
            e_load_mat(d0 + 4 * MATB, Bm + c0, t);
            e_load_mat(d0 + 5 * MATB, Bl + c0, t);
            asm volatile("cp.async.commit_group;" ::: "memory");
            asm volatile("cp.async.wait_group 1;" ::: "memory");
        } else {
            asm volatile("cp.async.wait_group 0;" ::: "memory");
        }
        __syncthreads();

        const uint32_t base = sb + p * BUFB;
#pragma unroll
        for (int k0 = 0; k0 < 32; k0 += 16) {
            uint32_t bh[4][2], bm[4][2], bl[4][2];
#pragma unroll
            for (int j = 0; j < 4; j++) {
                uint32_t boff = (uint32_t)((wm * 32 + j * 8) * ST + k0) * 2 + laneB;
                ldsm_x2(bh[j], base + 3 * MATB + boff);
                ldsm_x2(bm[j], base + 4 * MATB + boff);
                ldsm_x2(bl[j], base + 5 * MATB + boff);
            }
#pragma unroll
            for (int i = 0; i < 2; i++) {
                uint32_t aoff = (uint32_t)((wn * 32 + i * 16) * ST + k0) * 2 + laneA;
                uint32_t ah[4], am[4], al[4];
                ldsm_x4(ah, base + 0 * MATB + aoff);
                ldsm_x4(am, base + 1 * MATB + aoff);
                ldsm_x4(al, base + 2 * MATB + aoff);
#pragma unroll
                for (int j = 0; j < 4; j++) {
                    mma_bf16(acc[i][j], ah, bh[j]);
                    mma_bf16(acc[i][j], ah, bm[j]);
                    mma_bf16(acc[i][j], am, bh[j]);
                    mma_bf16(acc[i][j], am, bm[j]);
                    mma_bf16(acc[i][j], ah, bl[j]);
                    mma_bf16(acc[i][j], al, bh[j]);
                }
            }
        }
        __syncthreads();
    }

    const float scale = 0.08838834764831845f;
    float* Eb = g_E + (size_t)b * NN * NN;
#pragma unroll
    for (int i = 0; i < 2; i++) {
        int row = n0 + wn * 32 + i * 16 + g;
#pragma unroll
        for (int j = 0; j < 4; j++) {
            int col = m0 + wm * 32 + j * 8 + tg * 2;
            *(float2*)&Eb[(size_t)row * NN + col] =
                make_float2(acc[i][j][0] * scale, acc[i][j][1] * scale);
            *(float2*)&Eb[(size_t)(row + 8) * NN + col] =
                make_float2(acc[i][j][2] * scale, acc[i][j][3] * scale);
        }
    }
}

// ---------------- kernel 3: row max/sumexp + partial col sums, row-pairs ----------------
__global__ __launch_bounds__(256) void softscan_kernel() {
    __shared__ float redA[16], redB[16];
    const int b  = blockIdx.y;
    const int r0 = blockIdx.x * 16;
    const int t  = threadIdx.x;
    const int lane = t & 31, w = t >> 5;
    float colacc[8] = {0.f, 0.f, 0.f, 0.f, 0.f, 0.f, 0.f, 0.f};
    const float* Eb = g_E + (size_t)b * NN * NN;

    float v0[8], v1[8];
    {
        const float* Er0 = Eb + (size_t)r0 * NN;
        const float* Er1 = Eb + (size_t)(r0 + 1) * NN;
#pragma unroll
        for (int k = 0; k < 8; k++) { v0[k] = Er0[t + k * 256]; v1[k] = Er1[t + k * 256]; }
    }
    for (int rp = 0; rp < 8; rp++) {
        const int n = r0 + rp * 2;
        float w0[8], w1[8];
        if (rp < 7) {
            const float* Er0 = Eb + (size_t)(n + 2) * NN;
            const float* Er1 = Eb + (size_t)(n + 3) * NN;
#pragma unroll
            for (int k = 0; k < 8; k++) { w0[k] = Er0[t + k * 256]; w1[k] = Er1[t + k * 256]; }
        }
        float mx0 = -3.4e38f, mx1 = -3.4e38f;
#pragma unroll
        for (int k = 0; k < 8; k++) { mx0 = fmaxf(mx0, v0[k]); mx1 = fmaxf(mx1, v1[k]); }
#pragma unroll
        for (int o = 16; o; o >>= 1) {
            mx0 = fmaxf(mx0, __shfl_xor_sync(0xffffffffu, mx0, o));
            mx1 = fmaxf(mx1, __shfl_xor_sync(0xffffffffu, mx1, o));
        }
        if (lane == 0) { redA[w] = mx0; redA[8 + w] = mx1; }
        __syncthreads();
        mx0 = redA[0]; mx1 = redA[8];
#pragma unroll
        for (int i = 1; i < 8; i++) { mx0 = fmaxf(mx0, redA[i]); mx1 = fmaxf(mx1, redA[8 + i]); }

        float s0 = 0.f, s1 = 0.f;
#pragma unroll
        for (int k = 0; k < 8; k++) {
            v0[k] = __expf(v0[k] - mx0); s0 += v0[k];
            v1[k] = __expf(v1[k] - mx1); s1 += v1[k];
        }
#pragma unroll
        for (int o = 16; o; o >>= 1) {
            s0 += __shfl_xor_sync(0xffffffffu, s0, o);
            s1 += __shfl_xor_sync(0xffffffffu, s1, o);
        }
        if (lane == 0) { redB[w] = s0; redB[8 + w] = s1; }
        __syncthreads();
        s0 = redB[0]; s1 = redB[8];
#pragma unroll
        for (int i = 1; i < 8; i++) { s0 += redB[i]; s1 += redB[8 + i]; }

        if (t == 0) {
            g_rowmax[b * NN + n]     = mx0;
            g_rowsum[b * NN + n]     = s0;
            g_rowmax[b * NN + n + 1] = mx1;
            g_rowsum[b * NN + n + 1] = s1;
        }
        float i0 = 1.0f / s0, i1 = 1.0f / s1;
#pragma unroll
        for (int k = 0; k < 8; k++) colacc[k] += v0[k] * i0;
#pragma unroll
        for (int k = 0; k < 8; k++) colacc[k] += v1[k] * i1;
        if (rp < 7) {
#pragma unroll
            for (int k = 0; k < 8; k++) { v0[k] = w0[k]; v1[k] = w1[k]; }
        }
    }
    float* part = g_selpart + ((size_t)b * 128 + blockIdx.x) * NN;
#pragma unroll
    for (int k = 0; k < 8; k++) part[t + k * 256] = colacc[k];
}

// ---------------- kernel 3b: reduce partials — exact linear order, explicit MLP=32 ------
__global__ __launch_bounds__(128) void selsum_kernel() {
    const int b = blockIdx.y;
    const int m = blockIdx.x * 128 + threadIdx.x;
    const float* p = g_selpart + (size_t)b * 128 * NN + m;
    float s = 0.f;
    for (int i0 = 0; i0 < 128; i0 += 32) {
        float v[32];
#pragma unroll
        for (int j = 0; j < 32; j++) v[j] = p[(size_t)(i0 + j) * NN];
#pragma unroll
        for (int j = 0; j < 32; j++) s += v[j];   // same linear order -> bit-identical
    }
    g_sel[b * NN + m] = s;
}

// ---------------- kernel 4: stable top-k via rank counting ----------------
__global__ __launch_bounds__(256) void topk_kernel() {
    __shared__ float s[NN];
    const int b = blockIdx.y;
    for (int i = threadIdx.x; i < NN; i += 256) s[i] = g_sel[b * NN + i];
    __syncthreads();
    const int i  = blockIdx.x * 256 + threadIdx.x;
    const float vi = s[i];
    int rank = 0;
#pragma unroll 4
    for (int j = 0; j < NN; j++) {
        float vj = s[j];
        rank += (vj > vi) || (vj == vi && j < i);
    }
    if (rank < MM) g_idx[b * MM + rank] = i;
}

// ---------------- kernel 5: output GEMM via bf16x3 mma.sync, split-K=4 ----------------
#define ST2 72
#define OV_H 0
#define OV_L (128 * ST2 * 2)
#define OP_H (2 * 128 * ST2 * 2)
#define OP_L (OP_H + 64 * ST2 * 2)
#define O_SMEM (OP_L + 64 * ST2 * 2)

__global__ __launch_bounds__(256) void outgemm_tc_kernel() {
    extern __shared__ char osm[];
    __shared__ int   rows[64];
    __shared__ float rmax[64], rinv[64];
    const uint32_t sbase = smem_u32(osm);
    const int b = blockIdx.y, j0 = blockIdx.x * 64, z = blockIdx.z;
    const int t = threadIdx.x, lane = t & 31, wid = t >> 5;
    const int wc = wid & 3, wj = wid >> 2;
    const int g = lane >> 2, tg = lane & 3;

    if (t < 64) {
        int r   = g_idx[b * MM + j0 + t];
        rows[t] = r;
        rmax[t] = g_rowmax[b * NN + r];
        rinv[t] = 1.0f / g_rowsum[b * NN + r];
    }
    __syncthreads();

    const __nv_bfloat16* vh = g_vh + (size_t)b * C * NN;
    const __nv_bfloat16* vl = g_vl + (size_t)b * C * NN;
    const float* Eb = g_E + (size_t)b * NN * NN;

    const uint32_t laneA = (uint32_t)((lane & 15) * ST2 + (lane >> 4) * 8) * 2;
    const int l16 = lane & 15;
    const uint32_t laneB = (uint32_t)((l16 & 7) * ST2 + (l16 >> 3) * 8) * 2;

    float acc[2][4][4];
#pragma unroll
    for (int i = 0; i < 2; i++)
#pragma unroll
        for (int j = 0; j < 4; j++)
#pragma unroll
            for (int r = 0; r < 4; r++) acc[i][j][r] = 0.f;

    const int nBeg = z * (NN / 4);
    const int jj = t >> 2, q4 = t & 3;
    const float mxj = rmax[jj], ivj = rinv[jj];
    const size_t erow = (size_t)rows[jj] * NN;

    for (int n0 = nBeg; n0 < nBeg + NN / 4; n0 += 64) {
#pragma unroll
        for (int jld = 0; jld < 4; jld++) {
            int i = t + jld * 256;
            int c = i >> 3, k8 = i & 7;
            asm volatile("cp.async.cg.shared.global [%0], [%1], 16;"
                :: "r"(sbase + OV_H + (uint32_t)(c * ST2 + k8 * 8) * 2),
                   "l"(vh + (size_t)c * NN + n0 + k8 * 8));
            asm volatile("cp.async.cg.shared.global [%0], [%1], 16;"
                :: "r"(sbase + OV_L + (uint32_t)(c * ST2 + k8 * 8) * 2),
                   "l"(vl + (size_t)c * NN + n0 + k8 * 8));
        }
        asm volatile("cp.async.commit_group;" ::: "memory");

        {
            const float* Er = Eb + erow + n0 + q4 * 16;
#pragma unroll
            for (int i4 = 0; i4 < 4; i4++) {
                float4 e = *(const float4*)(Er + i4 * 4);
                float p0 = __expf(e.x - mxj) * ivj;
                float p1 = __expf(e.y - mxj) * ivj;
                float p2 = __expf(e.z - mxj) * ivj;
                float p3 = __expf(e.w - mxj) * ivj;
                __nv_bfloat16 h0 = __float2bfloat16_rn(p0);
                __nv_bfloat16 h1 = __float2bfloat16_rn(p1);
                __nv_bfloat16 h2 = __float2bfloat16_rn(p2);
                __nv_bfloat16 h3 = __float2bfloat16_rn(p3);
                __nv_bfloat16 l0 = __float2bfloat16_rn(p0 - __bfloat162float(h0));
                __nv_bfloat16 l1 = __float2bfloat16_rn(p1 - __bfloat162float(h1));
                __nv_bfloat16 l2 = __float2bfloat16_rn(p2 - __bfloat162float(h2));
                __nv_bfloat16 l3 = __float2bfloat16_rn(p3 - __bfloat162float(h3));
                uint32_t off = (uint32_t)(jj * ST2 + q4 * 16 + i4 * 4) * 2;
                *(__nv_bfloat162*)(osm + OP_H + off)     = __nv_bfloat162(h0, h1);
                *(__nv_bfloat162*)(osm + OP_H + off + 4) = __nv_bfloat162(h2, h3);
                *(__nv_bfloat162*)(osm + OP_L + off)     = __nv_bfloat162(l0, l1);
                *(__nv_bfloat162*)(osm + OP_L + off + 4) = __nv_bfloat162(l2, l3);
            }
        }
        asm volatile("cp.async.wait_group 0;" ::: "memory");
        __syncthreads();

#pragma unroll
        for (int k0 = 0; k0 < 64; k0 += 16) {
            uint32_t bh[4][2], bl[4][2];
#pragma unroll
            for (int nj = 0; nj < 4; nj++) {
                uint32_t boff = (uint32_t)((wj * 32 + nj * 8) * ST2 + k0) * 2 + laneB;
                ldsm_x2(bh[nj], sbase + OP_H + boff);
                ldsm_x2(bl[nj], sbase + OP_L + boff);
            }
#pragma unroll
            for (int mi = 0; mi < 2; mi++) {
                uint32_t aoff = (uint32_t)((wc * 32 + mi * 16) * ST2 + k0) * 2 + laneA;
                uint32_t ah[4], al[4];
                ldsm_x4(ah, sbase + OV_H + aoff);
                ldsm_x4(al, sbase + OV_L + aoff);
#pragma unroll
                for (int nj = 0; nj < 4; nj++) {
                    mma_bf16(acc[mi][nj], ah, bh[nj]);
                    mma_bf16(acc[mi][nj], ah, bl[nj]);
                    mma_bf16(acc[mi][nj], al, bh[nj]);
                }
            }
        }
        __syncthreads();
    }

    float* op = g_outpart[z];
#pragma unroll
    for (int mi = 0; mi < 2; mi++) {
        int c = wc * 32 + mi * 16 + g;
#pragma unroll
        for (int nj = 0; nj < 4; nj++) {
            int col = j0 + wj * 32 + nj * 8 + tg * 2;
            *(float2*)&op[((size_t)b * C + c) * MM + col] =
                make_float2(acc[mi][nj][0], acc[mi][nj][1]);
            *(float2*)&op[((size_t)b * C + c + 8) * MM + col] =
                make_float2(acc[mi][nj][2], acc[mi][nj][3]);
        }
    }
}

// ---------------- kernel 6: reduce split-K partials ----------------
__global__ __launch_bounds__(256) void outred_kernel(float* __restrict__ out) {
    const int i = blockIdx.x * 256 + threadIdx.x;
    out[i] = g_outpart[0][i] + g_outpart[1][i] + g_outpart[2][i] + g_outpart[3][i];
}

// ---------------- launch ----------------
extern "C" void kernel_launch(void* const* d_in, const int* in_sizes, int n_in,
                              void* d_out, int out_size) {
    const float* x  = (const float*)d_in[0];
    const float* Wq = (const float*)d_in[1];
    const float* Wk = (const float*)d_in[2];
    const float* Wv = (const float*)d_in[3];
    float* out = (float*)d_out;

    cudaFuncSetAttribute(qkv_kernel, cudaFuncAttributeMaxDynamicSharedMemorySize, 96 * 1024);
    cudaFuncSetAttribute(energy_bf16_kernel, cudaFuncAttributeMaxDynamicSharedMemorySize, E_SMEM);
    cudaFuncSetAttribute(outgemm_tc_kernel, cudaFuncAttributeMaxDynamicSharedMemorySize, O_SMEM);

    qkv_kernel<<<dim3(NN / 64, B, 3), 256, 96 * 1024>>>(x, Wq, Wk, Wv);
    energy_bf16_kernel<<<dim3(NN / 128, NN / 128, B), 512, E_SMEM>>>();
    softscan_kernel<<<dim3(NN / 16, B), 256>>>();
    selsum_kernel<<<dim3(NN / 128, B), 128>>>();
    topk_kernel<<<dim3(NN / 256, B), 256>>>();
    outgemm_tc_kernel<<<dim3(MM / 64, B, 4), 256, O_SMEM>>>();
    outred_kernel<<<(B * C * MM) / 256, 256>>>(out);
}

// round 16
// speedup vs baseline: 1.0407x; 1.0062x over previous
#include <cuda_runtime.h>
#include <cuda_bf16.h>
#include <math.h>
#include <stdint.h>

#define B 8
#define C 128
#define NN 2048
#define MM 512

// ---------------- scratch ----------------
__device__ __nv_bfloat16 g_qh[B * NN * C];
__device__ __nv_bfloat16 g_qm[B * NN * C];
__device__ __nv_bfloat16 g_ql[B * NN * C];
__device__ __nv_bfloat16 g_kh[B * NN * C];
__device__ __nv_bfloat16 g_km[B * NN * C];
__device__ __nv_bfloat16 g_kl[B * NN * C];
__device__ __nv_bfloat16 g_vh[B * C * NN];
__device__ __nv_bfloat16 g_vl[B * C * NN];
__device__ float g_E[(size_t)B * NN * NN];
__device__ float g_rowmax[B * NN];
__device__ float g_rowsum[B * NN];
__device__ float g_selpart[B * 128 * NN];
__device__ float g_sel[B * NN];
__device__ int   g_idx[B * MM];
__device__ float g_outpart[4][B * C * MM];

__device__ __forceinline__ uint32_t smem_u32(const void* p) {
    uint32_t a;
    asm("{ .reg .u64 t; cvta.to.shared.u64 t, %1; cvt.u32.u64 %0, t; }" : "=r"(a) : "l"(p));
    return a;
}
__device__ __forceinline__ void ldsm_x4(uint32_t* r, uint32_t a) {
    asm volatile("ldmatrix.sync.aligned.m8n8.x4.shared.b16 {%0,%1,%2,%3}, [%4];"
        : "=r"(r[0]), "=r"(r[1]), "=r"(r[2]), "=r"(r[3]) : "r"(a));
}
__device__ __forceinline__ void ldsm_x2(uint32_t* r, uint32_t a) {
    asm volatile("ldmatrix.sync.aligned.m8n8.x2.shared.b16 {%0,%1}, [%2];"
        : "=r"(r[0]), "=r"(r[1]) : "r"(a));
}
__device__ __forceinline__ void mma_bf16(float* d, const uint32_t* a, const uint32_t* b) {
    asm volatile("mma.sync.aligned.m16n8k16.row.col.f32.bf16.bf16.f32 "
        "{%0,%1,%2,%3}, {%4,%5,%6,%7}, {%8,%9}, {%0,%1,%2,%3};"
        : "+f"(d[0]), "+f"(d[1]), "+f"(d[2]), "+f"(d[3])
        : "r"(a[0]), "r"(a[1]), "r"(a[2]), "r"(a[3]), "r"(b[0]), "r"(b[1]));
}

// ---------------- kernel 1: q,k,v = W @ x; q,k split h/m/l to [N][C]; v split h/l -------
__global__ __launch_bounds__(256) void qkv_kernel(const float* __restrict__ x,
                                                  const float* __restrict__ Wq,
                                                  const float* __restrict__ Wk,
                                                  const float* __restrict__ Wv) {
    extern __shared__ float sm[];
    float* Ws = sm;
    float* xs = sm + C * C;
    const int b  = blockIdx.y;
    const int n0 = blockIdx.x * 64;
    const float* W = blockIdx.z == 0 ? Wq : (blockIdx.z == 1 ? Wk : Wv);
    const int t = threadIdx.x;

    for (int i = t; i < C * C; i += 256) Ws[i] = W[i];
    const float* xb = x + (size_t)b * C * NN;
    for (int i = t; i < C * 64; i += 256) {
        int c = i >> 6, n = i & 63;
        xs[i] = xb[(size_t)c * NN + n0 + n];
    }
    __syncthreads();

    const int tx = t & 15, ty = t >> 4;
    float acc[8][4];
#pragma unroll
    for (int i = 0; i < 8; i++)
#pragma unroll
        for (int j = 0; j < 4; j++) acc[i][j] = 0.f;

    for (int c = 0; c < C; c++) {
        float4 xv = *(const float4*)&xs[c * 64 + tx * 4];
#pragma unroll
        for (int i = 0; i < 8; i++) {
            float w = Ws[(ty * 8 + i) * C + c];
            acc[i][0] = fmaf(w, xv.x, acc[i][0]);
            acc[i][1] = fmaf(w, xv.y, acc[i][1]);
            acc[i][2] = fmaf(w, xv.z, acc[i][2]);
            acc[i][3] = fmaf(w, xv.w, acc[i][3]);
        }
    }

    if (blockIdx.z == 2) {
#pragma unroll
        for (int i = 0; i < 8; i++) {
            size_t o = ((size_t)b * C + ty * 8 + i) * NN + n0 + tx * 4;
            __nv_bfloat16 h[4], l[4];
#pragma unroll
            for (int j = 0; j < 4; j++) {
                h[j] = __float2bfloat16_rn(acc[i][j]);
                l[j] = __float2bfloat16_rn(acc[i][j] - __bfloat162float(h[j]));
            }
            *(__nv_bfloat162*)&g_vh[o]     = __nv_bfloat162(h[0], h[1]);
            *(__nv_bfloat162*)&g_vh[o + 2] = __nv_bfloat162(h[2], h[3]);
            *(__nv_bfloat162*)&g_vl[o]     = __nv_bfloat162(l[0], l[1]);
            *(__nv_bfloat162*)&g_vl[o + 2] = __nv_bfloat162(l[2], l[3]);
        }
    } else {
        __nv_bfloat16* dh = blockIdx.z == 0 ? g_qh : g_kh;
        __nv_bfloat16* dm = blockIdx.z == 0 ? g_qm : g_km;
        __nv_bfloat16* dl = blockIdx.z == 0 ? g_ql : g_kl;
#pragma unroll
        for (int j = 0; j < 4; j++) {
            __nv_bfloat16 h8[8], m8[8], l8[8];
#pragma unroll
            for (int i = 0; i < 8; i++) {
                float a = acc[i][j];
                __nv_bfloat16 h = __float2bfloat16_rn(a);
                float r1 = a - __bfloat162float(h);
                __nv_bfloat16 m = __float2bfloat16_rn(r1);
                float r2 = r1 - __bfloat162float(m);
                h8[i] = h; m8[i] = m; l8[i] = __float2bfloat16_rn(r2);
            }
            size_t o = ((size_t)b * NN + n0 + tx * 4 + j) * C + ty * 8;
            *(uint4*)&dh[o] = *(uint4*)h8;
            *(uint4*)&dm[o] = *(uint4*)m8;
            *(uint4*)&dl[o] = *(uint4*)l8;
        }
    }
}

// ---------------- kernel 2: E via bf16x6 mma.sync; 512 threads ----------------
#define ST 40
#define MATB (128 * ST * 2)
#define BUFB (6 * MATB)
#define E_SMEM (2 * BUFB)

__device__ __forceinline__ void e_load_mat(uint32_t dst, const __nv_bfloat16* src, int t) {
    int r = t >> 2, k8 = t & 3;
    asm volatile("cp.async.cg.shared.global [%0], [%1], 16;"
        :: "r"(dst + (uint32_t)(r * ST + k8 * 8) * 2),
           "l"(src + (size_t)r * C + k8 * 8));
}

__global__ __launch_bounds__(512) void energy_bf16_kernel() {
    extern __shared__ char esm[];
    const uint32_t sb = smem_u32(esm);
    const int b = blockIdx.z, n0 = blockIdx.y * 128, m0 = blockIdx.x * 128;
    const int t = threadIdx.x, lane = t & 31, wid = t >> 5;
    const int wn = wid >> 2, wm = wid & 3;
    const int g = lane >> 2, tg = lane & 3;

    const __nv_bfloat16* Ah = g_qh + ((size_t)b * NN + n0) * C;
    const __nv_bfloat16* Am = g_qm + ((size_t)b * NN + n0) * C;
    const __nv_bfloat16* Al = g_ql + ((size_t)b * NN + n0) * C;
    const __nv_bfloat16* Bh = g_kh + ((size_t)b * NN + m0) * C;
    const __nv_bfloat16* Bm = g_km + ((size_t)b * NN + m0) * C;
    const __nv_bfloat16* Bl = g_kl + ((size_t)b * NN + m0) * C;

    const uint32_t laneA = (uint32_t)((lane & 15) * ST + (lane >> 4) * 8) * 2;
    const int l16 = lane & 15;
    const uint32_t laneB = (uint32_t)((l16 & 7) * ST + (l16 >> 3) * 8) * 2;

    float acc[2][4][4];
#pragma unroll
    for (int i = 0; i < 2; i++)
#pragma unroll
        for (int j = 0; j < 4; j++)
#pragma unroll
            for (int r = 0; r < 4; r++) acc[i][j][r] = 0.f;

    {
        uint32_t d0 = sb;
        e_load_mat(d0 + 0 * MATB, Ah, t);
        e_load_mat(d0 + 1 * MATB, Am, t);
        e_load_mat(d0 + 2 * MATB, Al, t);
        e_load_mat(d0 + 3 * MATB, Bh, t);
        e_load_mat(d0 + 4 * MATB, Bm, t);
        e_load_mat(d0 + 5 * MATB, Bl, t);
        asm volatile("cp.async.commit_group;" ::: "memory");
    }

    for (int ch = 0; ch < 4; ch++) {
        const int p = ch & 1;
        if (ch < 3) {
            const int c0 = (ch + 1) * 32;
            uint32_t d0 = sb + (p ^ 1) * BUFB;
            e_load_mat(d0 + 0 * MATB, Ah + c0, t);
            e_load_mat(d0 + 1 * MATB, Am + c0, t);
            e_load_mat(d0 + 2 * MATB, Al + c0, t);
            e_load_mat(d0 + 3 * MATB, Bh + c0, t);
            e_load_mat(d0 + 4 * MATB, Bm + c0, t);
            e_load_mat(d0 + 5 * MATB, Bl + c0, t);
            asm volatile("cp.async.commit_group;" ::: "memory");
            asm volatile("cp.async.wait_group 1;" ::: "memory");
        } else {
            asm volatile("cp.async.wait_group 0;" ::: "memory");
        }
        __syncthreads();

        const uint32_t base = sb + p * BUFB;
#pragma unroll
        for (int k0 = 0; k0 < 32; k0 += 16) {
            uint32_t bh[4][2], bm[4][2], bl[4][2];
#pragma unroll
            for (int j = 0; j < 4; j++) {
                uint32_t boff = (uint32_t)((wm * 32 + j * 8) * ST + k0) * 2 + laneB;
                ldsm_x2(bh[j], base + 3 * MATB + boff);
                ldsm_x2(bm[j], base + 4 * MATB + boff);
                ldsm_x2(bl[j], base + 5 * MATB + boff);
            }
#pragma unroll
            for (int i = 0; i < 2; i++) {
                uint32_t aoff = (uint32_t)((wn * 32 + i * 16) * ST + k0) * 2 + laneA;
                uint32_t ah[4], am[4], al[4];
                ldsm_x4(ah, base + 0 * MATB + aoff);
                ldsm_x4(am, base + 1 * MATB + aoff);
                ldsm_x4(al, base + 2 * MATB + aoff);
#pragma unroll
                for (int j = 0; j < 4; j++) {
                    mma_bf16(acc[i][j], ah, bh[j]);
                    mma_bf16(acc[i][j], ah, bm[j]);
                    mma_bf16(acc[i][j], am, bh[j]);
                    mma_bf16(acc[i][j], am, bm[j]);
                    mma_bf16(acc[i][j], ah, bl[j]);
                    mma_bf16(acc[i][j], al, bh[j]);
                }
            }
        }
        __syncthreads();
    }

    const float scale = 0.08838834764831845f;
    float* Eb = g_E + (size_t)b * NN * NN;
#pragma unroll
    for (int i = 0; i < 2; i++) {
        int row = n0 + wn * 32 + i * 16 + g;
#pragma unroll
        for (int j = 0; j < 4; j++) {
            int col = m0 + wm * 32 + j * 8 + tg * 2;
            *(float2*)&Eb[(size_t)row * NN + col] =
                make_float2(acc[i][j][0] * scale, acc[i][j][1] * scale);
            *(float2*)&Eb[(size_t)(row + 8) * NN + col] =
                make_float2(acc[i][j][2] * scale, acc[i][j][3] * scale);
        }
    }
}

// ---------------- kernel 3: row max/sumexp + partial col sums, row-pairs ----------------
__global__ __launch_bounds__(256) void softscan_kernel() {
    __shared__ float redA[16], redB[16];
    const int b  = blockIdx.y;
    const int r0 = blockIdx.x * 16;
    const int t  = threadIdx.x;
    const int lane = t & 31, w = t >> 5;
    float colacc[8] = {0.f, 0.f, 0.f, 0.f, 0.f, 0.f, 0.f, 0.f};
    const float* Eb = g_E + (size_t)b * NN * NN;

    float v0[8], v1[8];
    {
        const float* Er0 = Eb + (size_t)r0 * NN;
        const float* Er1 = Eb + (size_t)(r0 + 1) * NN;
#pragma unroll
        for (int k = 0; k < 8; k++) { v0[k] = Er0[t + k * 256]; v1[k] = Er1[t + k * 256]; }
    }
    for (int rp = 0; rp < 8; rp++) {
        const int n = r0 + rp * 2;
        float w0[8], w1[8];
        if (rp < 7) {
            const float* Er0 = Eb + (size_t)(n + 2) * NN;
            const float* Er1 = Eb + (size_t)(n + 3) * NN;
#pragma unroll
            for (int k = 0; k < 8; k++) { w0[k] = Er0[t + k * 256]; w1[k] = Er1[t + k * 256]; }
        }
        float mx0 = -3.4e38f, mx1 = -3.4e38f;
#pragma unroll
        for (int k = 0; k < 8; k++) { mx0 = fmaxf(mx0, v0[k]); mx1 = fmaxf(mx1, v1[k]); }
#pragma unroll
        for (int o = 16; o; o >>= 1) {
            mx0 = fmaxf(mx0, __shfl_xor_sync(0xffffffffu, mx0, o));
            mx1 = fmaxf(mx1, __shfl_xor_sync(0xffffffffu, mx1, o));
        }
        if (lane == 0) { redA[w] = mx0; redA[8 + w] = mx1; }
        __syncthreads();
        mx0 = redA[0]; mx1 = redA[8];
#pragma unroll
        for (int i = 1; i < 8; i++) { mx0 = fmaxf(mx0, redA[i]); mx1 = fmaxf(mx1, redA[8 + i]); }

        float s0 = 0.f, s1 = 0.f;
#pragma unroll
        for (int k = 0; k < 8; k++) {
            v0[k] = __expf(v0[k] - mx0); s0 += v0[k];
            v1[k] = __expf(v1[k] - mx1); s1 += v1[k];
        }
#pragma unroll
        for (int o = 16; o; o >>= 1) {
            s0 += __shfl_xor_sync(0xffffffffu, s0, o);
            s1 += __shfl_xor_sync(0xffffffffu, s1, o);
        }
        if (lane == 0) { redB[w] = s0; redB[8 + w] = s1; }
        __syncthreads();
        s0 = redB[0]; s1 = redB[8];
#pragma unroll
        for (int i = 1; i < 8; i++) { s0 += redB[i]; s1 += redB[8 + i]; }

        if (t == 0) {
            g_rowmax[b * NN + n]     = mx0;
            g_rowsum[b * NN + n]     = s0;
            g_rowmax[b * NN + n + 1] = mx1;
            g_rowsum[b * NN + n + 1] = s1;
        }
        float i0 = 1.0f / s0, i1 = 1.0f / s1;
#pragma unroll
        for (int k = 0; k < 8; k++) colacc[k] += v0[k] * i0;
#pragma unroll
        for (int k = 0; k < 8; k++) colacc[k] += v1[k] * i1;
        if (rp < 7) {
#pragma unroll
            for (int k = 0; k < 8; k++) { v0[k] = w0[k]; v1[k] = w1[k]; }
        }
    }
    float* part = g_selpart + ((size_t)b * 128 + blockIdx.x) * NN;
#pragma unroll
    for (int k = 0; k < 8; k++) part[t + k * 256] = colacc[k];
}

// ---------------- kernel 3b: reduce partials — cp.async staging, exact linear order -----
// Thread t copies column (m0+t)'s 128 terms to smem via async-proxy (register-free MLP),
// then sums them from smem in the identical linear order -> bit-identical g_sel.
#define SEL_SMEM (128 * 128 * 4)
__global__ __launch_bounds__(128) void selsum_kernel() {
    extern __shared__ float sbuf[];   // [term][col] = [128][128]
    const int b = blockIdx.y;
    const int t = threadIdx.x;
    const int m = blockIdx.x * 128 + t;
    const float* p = g_selpart + (size_t)b * 128 * NN + m;
    const uint32_t sb = smem_u32(sbuf);

#pragma unroll 16
    for (int i = 0; i < 128; i++) {
        asm volatile("cp.async.ca.shared.global [%0], [%1], 4;"
            :: "r"(sb + (uint32_t)(i * 128 + t) * 4), "l"(p + (size_t)i * NN));
    }
    asm volatile("cp.async.commit_group;" ::: "memory");
    asm volatile("cp.async.wait_group 0;" ::: "memory");

    float s = 0.f;
#pragma unroll 16
    for (int i = 0; i < 128; i++) s += sbuf[i * 128 + t];   // same linear order
    g_sel[b * NN + m] = s;
}

// ---------------- kernel 4: stable top-k via rank counting ----------------
__global__ __launch_bounds__(256) void topk_kernel() {
    __shared__ float s[NN];
    const int b = blockIdx.y;
    for (int i = threadIdx.x; i < NN; i += 256) s[i] = g_sel[b * NN + i];
    __syncthreads();
    const int i  = blockIdx.x * 256 + threadIdx.x;
    const float vi = s[i];
    int rank = 0;
#pragma unroll 4
    for (int j = 0; j < NN; j++) {
        float vj = s[j];
        rank += (vj > vi) || (vj == vi && j < i);
    }
    if (rank < MM) g_idx[b * MM + rank] = i;
}

// ---------------- kernel 5: output GEMM via bf16x3 mma.sync, split-K=4 ----------------
#define ST2 72
#define OV_H 0
#define OV_L (128 * ST2 * 2)
#define OP_H (2 * 128 * ST2 * 2)
#define OP_L (OP_H + 64 * ST2 * 2)
#define O_SMEM (OP_L + 64 * ST2 * 2)

__global__ __launch_bounds__(256) void outgemm_tc_kernel() {
    extern __shared__ char osm[];
    __shared__ int   rows[64];
    __shared__ float rmax[64], rinv[64];
    const uint32_t sbase = smem_u32(osm);
    const int b = blockIdx.y, j0 = blockIdx.x * 64, z = blockIdx.z;
    const int t = threadIdx.x, lane = t & 31, wid = t >> 5;
    const int wc = wid & 3, wj = wid >> 2;
    const int g = lane >> 2, tg = lane & 3;

    if (t < 64) {
        int r   = g_idx[b * MM + j0 + t];
        rows[t] = r;
        rmax[t] = g_rowmax[b * NN + r];
        rinv[t] = 1.0f / g_rowsum[b * NN + r];
    }
    __syncthreads();

    const __nv_bfloat16* vh = g_vh + (size_t)b * C * NN;
    const __nv_bfloat16* vl = g_vl + (size_t)b * C * NN;
    const float* Eb = g_E + (size_t)b * NN * NN;

    const uint32_t laneA = (uint32_t)((lane & 15) * ST2 + (lane >> 4) * 8) * 2;
    const int l16 = lane & 15;
    const uint32_t laneB = (uint32_t)((l16 & 7) * ST2 + (l16 >> 3) * 8) * 2;

    float acc[2][4][4];
#pragma unroll
    for (int i = 0; i < 2; i++)
#pragma unroll
        for (int j = 0; j < 4; j++)
#pragma unroll
            for (int r = 0; r < 4; r++) acc[i][j][r] = 0.f;

    const int nBeg = z * (NN / 4);
    const int jj = t >> 2, q4 = t & 3;
    const float mxj = rmax[jj], ivj = rinv[jj];
    const size_t erow = (size_t)rows[jj] * NN;

    for (int n0 = nBeg; n0 < nBeg + NN / 4; n0 += 64) {
#pragma unroll
        for (int jld = 0; jld < 4; jld++) {
            int i = t + jld * 256;
            int c = i >> 3, k8 = i & 7;
            asm volatile("cp.async.cg.shared.global [%0], [%1], 16;"
                :: "r"(sbase + OV_H + (uint32_t)(c * ST2 + k8 * 8) * 2),
                   "l"(vh + (size_t)c * NN + n0 + k8 * 8));
            asm volatile("cp.async.cg.shared.global [%0], [%1], 16;"
                :: "r"(sbase + OV_L + (uint32_t)(c * ST2 + k8 * 8) * 2),
                   "l"(vl + (size_t)c * NN + n0 + k8 * 8));
        }
        asm volatile("cp.async.commit_group;" ::: "memory");

        {
            const float* Er = Eb + erow + n0 + q4 * 16;
#pragma unroll
            for (int i4 = 0; i4 < 4; i4++) {
                float4 e = *(const float4*)(Er + i4 * 4);
                float p0 = __expf(e.x - mxj) * ivj;
                float p1 = __expf(e.y - mxj) * ivj;
                float p2 = __expf(e.z - mxj) * ivj;
                float p3 = __expf(e.w - mxj) * ivj;
                __nv_bfloat16 h0 = __float2bfloat16_rn(p0);
                __nv_bfloat16 h1 = __float2bfloat16_rn(p1);
                __nv_bfloat16 h2 = __float2bfloat16_rn(p2);
                __nv_bfloat16 h3 = __float2bfloat16_rn(p3);
                __nv_bfloat16 l0 = __float2bfloat16_rn(p0 - __bfloat162float(h0));
                __nv_bfloat16 l1 = __float2bfloat16_rn(p1 - __bfloat162float(h1));
                __nv_bfloat16 l2 = __float2bfloat16_rn(p2 - __bfloat162float(h2));
                __nv_bfloat16 l3 = __float2bfloat16_rn(p3 - __bfloat162float(h3));
                uint32_t off = (uint32_t)(jj * ST2 + q4 * 16 + i4 * 4) * 2;
                *(__nv_bfloat162*)(osm + OP_H + off)     = __nv_bfloat162(h0, h1);
                *(__nv_bfloat162*)(osm + OP_H + off + 4) = __nv_bfloat162(h2, h3);
                *(__nv_bfloat162*)(osm + OP_L + off)     = __nv_bfloat162(l0, l1);
                *(__nv_bfloat162*)(osm + OP_L + off + 4) = __nv_bfloat162(l2, l3);
            }
        }
        asm volatile("cp.async.wait_group 0;" ::: "memory");
        __syncthreads();

#pragma unroll
        for (int k0 = 0; k0 < 64; k0 += 16) {
            uint32_t bh[4][2], bl[4][2];
#pragma unroll
            for (int nj = 0; nj < 4; nj++) {
                uint32_t boff = (uint32_t)((wj * 32 + nj * 8) * ST2 + k0) * 2 + laneB;
                ldsm_x2(bh[nj], sbase + OP_H + boff);
                ldsm_x2(bl[nj], sbase + OP_L + boff);
            }
#pragma unroll
            for (int mi = 0; mi < 2; mi++) {
                uint32_t aoff = (uint32_t)((wc * 32 + mi * 16) * ST2 + k0) * 2 + laneA;
                uint32_t ah[4], al[4];
                ldsm_x4(ah, sbase + OV_H + aoff);
                ldsm_x4(al, sbase + OV_L + aoff);
#pragma unroll
                for (int nj = 0; nj < 4; nj++) {
                    mma_bf16(acc[mi][nj], ah, bh[nj]);
                    mma_bf16(acc[mi][nj], ah, bl[nj]);
                    mma_bf16(acc[mi][nj], al, bh[nj]);
                }
            }
        }
        __syncthreads();
    }

    float* op = g_outpart[z];
#pragma unroll
    for (int mi = 0; mi < 2; mi++) {
        int c = wc * 32 + mi * 16 + g;
#pragma unroll
        for (int nj = 0; nj < 4; nj++) {
            int col = j0 + wj * 32 + nj * 8 + tg * 2;
            *(float2*)&op[((size_t)b * C + c) * MM + col] =
                make_float2(acc[mi][nj][0], acc[mi][nj][1]);
            *(float2*)&op[((size_t)b * C + c + 8) * MM + col] =
                make_float2(acc[mi][nj][2], acc[mi][nj][3]);
        }
    }
}

// ---------------- kernel 6: reduce split-K partials ----------------
__global__ __launch_bounds__(256) void outred_kernel(float* __restrict__ out) {
    const int i = blockIdx.x * 256 + threadIdx.x;
    out[i] = g_outpart[0][i] + g_outpart[1][i] + g_outpart[2][i] + g_outpart[3][i];
}

// ---------------- launch ----------------
extern "C" void kernel_launch(void* const* d_in, const int* in_sizes, int n_in,
                              void* d_out, int out_size) {
    const float* x  = (const float*)d_in[0];
    const float* Wq = (const float*)d_in[1];
    const float* Wk = (const float*)d_in[2];
    const float* Wv = (const float*)d_in[3];
    float* out = (float*)d_out;

    cudaFuncSetAttribute(qkv_kernel, cudaFuncAttributeMaxDynamicSharedMemorySize, 96 * 1024);
    cudaFuncSetAttribute(energy_bf16_kernel, cudaFuncAttributeMaxDynamicSharedMemorySize, E_SMEM);
    cudaFuncSetAttribute(outgemm_tc_kernel, cudaFuncAttributeMaxDynamicSharedMemorySize, O_SMEM);
    cudaFuncSetAttribute(selsum_kernel, cudaFuncAttributeMaxDynamicSharedMemorySize, SEL_SMEM);

    qkv_kernel<<<dim3(NN / 64, B, 3), 256, 96 * 1024>>>(x, Wq, Wk, Wv);
    energy_bf16_kernel<<<dim3(NN / 128, NN / 128, B), 512, E_SMEM>>>();
    softscan_kernel<<<dim3(NN / 16, B), 256>>>();
    selsum_kernel<<<dim3(NN / 128, B), 128, SEL_SMEM>>>();
    topk_kernel<<<dim3(NN / 256, B), 256>>>();
    outgemm_tc_kernel<<<dim3(MM / 64, B, 4), 256, O_SMEM>>>();
    outred_kernel<<<(B * C * MM) / 256, 256>>>(out);
}

// round 17
// speedup vs baseline: 1.0591x; 1.0177x over previous
#include <cuda_runtime.h>
#include <cuda_bf16.h>
#include <math.h>
#include <stdint.h>

#define B 8
#define C 128
#define NN 2048
#define MM 512

// ---------------- scratch ----------------
__device__ __nv_bfloat16 g_qh[B * NN * C];
__device__ __nv_bfloat16 g_qm[B * NN * C];
__device__ __nv_bfloat16 g_ql[B * NN * C];
__device__ __nv_bfloat16 g_kh[B * NN * C];
__device__ __nv_bfloat16 g_km[B * NN * C];
__device__ __nv_bfloat16 g_kl[B * NN * C];
__device__ __nv_bfloat16 g_vh[B * C * NN];
__device__ __nv_bfloat16 g_vl[B * C * NN];
__device__ float g_E[(size_t)B * NN * NN];
__device__ float g_rowmax[B * NN];
__device__ float g_rowsum[B * NN];
__device__ float g_selpart[B * 128 * NN];
__device__ float g_sel[B * NN];
__device__ int   g_idx[B * MM];
__device__ float g_outpart[4][B * C * MM];

__device__ __forceinline__ uint32_t smem_u32(const void* p) {
    uint32_t a;
    asm("{ .reg .u64 t; cvta.to.shared.u64 t, %1; cvt.u32.u64 %0, t; }" : "=r"(a) : "l"(p));
    return a;
}
__device__ __forceinline__ void ldsm_x4(uint32_t* r, uint32_t a) {
    asm volatile("ldmatrix.sync.aligned.m8n8.x4.shared.b16 {%0,%1,%2,%3}, [%4];"
        : "=r"(r[0]), "=r"(r[1]), "=r"(r[2]), "=r"(r[3]) : "r"(a));
}
__device__ __forceinline__ void ldsm_x2(uint32_t* r, uint32_t a) {
    asm volatile("ldmatrix.sync.aligned.m8n8.x2.shared.b16 {%0,%1}, [%2];"
        : "=r"(r[0]), "=r"(r[1]) : "r"(a));
}
__device__ __forceinline__ void mma_bf16(float* d, const uint32_t* a, const uint32_t* b) {
    asm volatile("mma.sync.aligned.m16n8k16.row.col.f32.bf16.bf16.f32 "
        "{%0,%1,%2,%3}, {%4,%5,%6,%7}, {%8,%9}, {%0,%1,%2,%3};"
        : "+f"(d[0]), "+f"(d[1]), "+f"(d[2]), "+f"(d[3])
        : "r"(a[0]), "r"(a[1]), "r"(a[2]), "r"(a[3]), "r"(b[0]), "r"(b[1]));
}

// ---------------- kernel 1: q,k,v = W @ x; q,k split h/m/l to [N][C]; v split h/l -------
__global__ __launch_bounds__(256) void qkv_kernel(const float* __restrict__ x,
                                                  const float* __restrict__ Wq,
                                                  const float* __restrict__ Wk,
                                                  const float* __restrict__ Wv) {
    extern __shared__ float sm[];
    float* Ws = sm;
    float* xs = sm + C * C;
    const int b  = blockIdx.y;
    const int n0 = blockIdx.x * 64;
    const float* W = blockIdx.z == 0 ? Wq : (blockIdx.z == 1 ? Wk : Wv);
    const int t = threadIdx.x;

    for (int i = t; i < C * C; i += 256) Ws[i] = W[i];
    const float* xb = x + (size_t)b * C * NN;
    for (int i = t; i < C * 64; i += 256) {
        int c = i >> 6, n = i & 63;
        xs[i] = xb[(size_t)c * NN + n0 + n];
    }
    __syncthreads();

    const int tx = t & 15, ty = t >> 4;
    float acc[8][4];
#pragma unroll
    for (int i = 0; i < 8; i++)
#pragma unroll
        for (int j = 0; j < 4; j++) acc[i][j] = 0.f;

    for (int c = 0; c < C; c++) {
        float4 xv = *(const float4*)&xs[c * 64 + tx * 4];
#pragma unroll
        for (int i = 0; i < 8; i++) {
            float w = Ws[(ty * 8 + i) * C + c];
            acc[i][0] = fmaf(w, xv.x, acc[i][0]);
            acc[i][1] = fmaf(w, xv.y, acc[i][1]);
            acc[i][2] = fmaf(w, xv.z, acc[i][2]);
            acc[i][3] = fmaf(w, xv.w, acc[i][3]);
        }
    }

    if (blockIdx.z == 2) {
#pragma unroll
        for (int i = 0; i < 8; i++) {
            size_t o = ((size_t)b * C + ty * 8 + i) * NN + n0 + tx * 4;
            __nv_bfloat16 h[4], l[4];
#pragma unroll
            for (int j = 0; j < 4; j++) {
                h[j] = __float2bfloat16_rn(acc[i][j]);
                l[j] = __float2bfloat16_rn(acc[i][j] - __bfloat162float(h[j]));
            }
            *(__nv_bfloat162*)&g_vh[o]     = __nv_bfloat162(h[0], h[1]);
            *(__nv_bfloat162*)&g_vh[o + 2] = __nv_bfloat162(h[2], h[3]);
            *(__nv_bfloat162*)&g_vl[o]     = __nv_bfloat162(l[0], l[1]);
            *(__nv_bfloat162*)&g_vl[o + 2] = __nv_bfloat162(l[2], l[3]);
        }
    } else {
        __nv_bfloat16* dh = blockIdx.z == 0 ? g_qh : g_kh;
        __nv_bfloat16* dm = blockIdx.z == 0 ? g_qm : g_km;
        __nv_bfloat16* dl = blockIdx.z == 0 ? g_ql : g_kl;
#pragma unroll
        for (int j = 0; j < 4; j++) {
            __nv_bfloat16 h8[8], m8[8], l8[8];
#pragma unroll
            for (int i = 0; i < 8; i++) {
                float a = acc[i][j];
                __nv_bfloat16 h = __float2bfloat16_rn(a);
                float r1 = a - __bfloat162float(h);
                __nv_bfloat16 m = __float2bfloat16_rn(r1);
                float r2 = r1 - __bfloat162float(m);
                h8[i] = h; m8[i] = m; l8[i] = __float2bfloat16_rn(r2);
            }
            size_t o = ((size_t)b * NN + n0 + tx * 4 + j) * C + ty * 8;
            *(uint4*)&dh[o] = *(uint4*)h8;
            *(uint4*)&dm[o] = *(uint4*)m8;
            *(uint4*)&dl[o] = *(uint4*)l8;
        }
    }
}

// ---------------- kernel 2: E via bf16x6 mma.sync; 512 threads ----------------
#define ST 40
#define MATB (128 * ST * 2)
#define BUFB (6 * MATB)
#define E_SMEM (2 * BUFB)

__device__ __forceinline__ void e_load_mat(uint32_t dst, const __nv_bfloat16* src, int t) {
    int r = t >> 2, k8 = t & 3;
    asm volatile("cp.async.cg.shared.global [%0], [%1], 16;"
        :: "r"(dst + (uint32_t)(r * ST + k8 * 8) * 2),
           "l"(src + (size_t)r * C + k8 * 8));
}

__global__ __launch_bounds__(512) void energy_bf16_kernel() {
    extern __shared__ char esm[];
    const uint32_t sb = smem_u32(esm);
    const int b = blockIdx.z, n0 = blockIdx.y * 128, m0 = blockIdx.x * 128;
    const int t = threadIdx.x, lane = t & 31, wid = t >> 5;
    const int wn = wid >> 2, wm = wid & 3;
    const int g = lane >> 2, tg = lane & 3;

    const __nv_bfloat16* Ah = g_qh + ((size_t)b * NN + n0) * C;
    const __nv_bfloat16* Am = g_qm + ((size_t)b * NN + n0) * C;
    const __nv_bfloat16* Al = g_ql + ((size_t)b * NN + n0) * C;
    const __nv_bfloat16* Bh = g_kh + ((size_t)b * NN + m0) * C;
    const __nv_bfloat16* Bm = g_km + ((size_t)b * NN + m0) * C;
    const __nv_bfloat16* Bl = g_kl + ((size_t)b * NN + m0) * C;

    const uint32_t laneA = (uint32_t)((lane & 15) * ST + (lane >> 4) * 8) * 2;
    const int l16 = lane & 15;
    const uint32_t laneB = (uint32_t)((l16 & 7) * ST + (l16 >> 3) * 8) * 2;

    float acc[2][4][4];
#pragma unroll
    for (int i = 0; i < 2; i++)
#pragma unroll
        for (int j = 0; j < 4; j++)
#pragma unroll
            for (int r = 0; r < 4; r++) acc[i][j][r] = 0.f;

    {
        uint32_t d0 = sb;
        e_load_mat(d0 + 0 * MATB, Ah, t);
        e_load_mat(d0 + 1 * MATB, Am, t);
        e_load_mat(d0 + 2 * MATB, Al, t);
        e_load_mat(d0 + 3 * MATB, Bh, t);
        e_load_mat(d0 + 4 * MATB, Bm, t);
        e_load_mat(d0 + 5 * MATB, Bl, t);
        asm volatile("cp.async.commit_group;" ::: "memory");
    }

    for (int ch = 0; ch < 4; ch++) {
        const int p = ch & 1;
        if (ch < 3) {
            const int c0 = (ch + 1) * 32;
            uint32_t d0 = sb + (p ^ 1) * BUFB;
            e_load_mat(d0 + 0 * MATB, Ah + c0, t);
            e_load_mat(d0 + 1 * MATB, Am + c0, t);
            e_load_mat(d0 + 2 * MATB, Al + c0, t);
            e_load_mat(d0 + 3 * MATB, Bh + c0, t);
            e_load_mat(d0 + 4 * MATB, Bm + c0, t);
            e_load_mat(d0 + 5 * MATB, Bl + c0, t);
            asm volatile("cp.async.commit_group;" ::: "memory");
            asm volatile("cp.async.wait_group 1;" ::: "memory");
        } else {
            asm volatile("cp.async.wait_group 0;" ::: "memory");
        }
        __syncthreads();

        const uint32_t base = sb + p * BUFB;
#pragma unroll
        for (int k0 = 0; k0 < 32; k0 += 16) {
            uint32_t bh[4][2], bm[4][2], bl[4][2];
#pragma unroll
            for (int j = 0; j < 4; j++) {
                uint32_t boff = (uint32_t)((wm * 32 + j * 8) * ST + k0) * 2 + laneB;
                ldsm_x2(bh[j], base + 3 * MATB + boff);
                ldsm_x2(bm[j], base + 4 * MATB + boff);
                ldsm_x2(bl[j], base + 5 * MATB + boff);
            }
#pragma unroll
            for (int i = 0; i < 2; i++) {
                uint32_t aoff = (uint32_t)((wn * 32 + i * 16) * ST + k0) * 2 + laneA;
                uint32_t ah[4], am[4], al[4];
                ldsm_x4(ah, base + 0 * MATB + aoff);
                ldsm_x4(am, base + 1 * MATB + aoff);
                ldsm_x4(al, base + 2 * MATB + aoff);
#pragma unroll
                for (int j = 0; j < 4; j++) {
                    mma_bf16(acc[i][j], ah, bh[j]);
                    mma_bf16(acc[i][j], ah, bm[j]);
                    mma_bf16(acc[i][j], am, bh[j]);
                    mma_bf16(acc[i][j], am, bm[j]);
                    mma_bf16(acc[i][j], ah, bl[j]);
                    mma_bf16(acc[i][j], al, bh[j]);
                }
            }
        }
        __syncthreads();
    }

    const float scale = 0.08838834764831845f;
    float* Eb = g_E + (size_t)b * NN * NN;
#pragma unroll
    for (int i = 0; i < 2; i++) {
        int row = n0 + wn * 32 + i * 16 + g;
#pragma unroll
        for (int j = 0; j < 4; j++) {
            int col = m0 + wm * 32 + j * 8 + tg * 2;
            *(float2*)&Eb[(size_t)row * NN + col] =
                make_float2(acc[i][j][0] * scale, acc[i][j][1] * scale);
            *(float2*)&Eb[(size_t)(row + 8) * NN + col] =
                make_float2(acc[i][j][2] * scale, acc[i][j][3] * scale);
        }
    }
}

// ---------------- kernel 3: row max/sumexp + partial col sums, row-pairs ----------------
__global__ __launch_bounds__(256) void softscan_kernel() {
    __shared__ float redA[16], redB[16];
    const int b  = blockIdx.y;
    const int r0 = blockIdx.x * 16;
    const int t  = threadIdx.x;
    const int lane = t & 31, w = t >> 5;
    float colacc[8] = {0.f, 0.f, 0.f, 0.f, 0.f, 0.f, 0.f, 0.f};
    const float* Eb = g_E + (size_t)b * NN * NN;

    float v0[8], v1[8];
    {
        const float* Er0 = Eb + (size_t)r0 * NN;
        const float* Er1 = Eb + (size_t)(r0 + 1) * NN;
#pragma unroll
        for (int k = 0; k < 8; k++) { v0[k] = Er0[t + k * 256]; v1[k] = Er1[t + k * 256]; }
    }
    for (int rp = 0; rp < 8; rp++) {
        const int n = r0 + rp * 2;
        float w0[8], w1[8];
        if (rp < 7) {
            const float* Er0 = Eb + (size_t)(n + 2) * NN;
            const float* Er1 = Eb + (size_t)(n + 3) * NN;
#pragma unroll
            for (int k = 0; k < 8; k++) { w0[k] = Er0[t + k * 256]; w1[k] = Er1[t + k * 256]; }
        }
        float mx0 = -3.4e38f, mx1 = -3.4e38f;
#pragma unroll
        for (int k = 0; k < 8; k++) { mx0 = fmaxf(mx0, v0[k]); mx1 = fmaxf(mx1, v1[k]); }
#pragma unroll
        for (int o = 16; o; o >>= 1) {
            mx0 = fmaxf(mx0, __shfl_xor_sync(0xffffffffu, mx0, o));
            mx1 = fmaxf(mx1, __shfl_xor_sync(0xffffffffu, mx1, o));
        }
        if (lane == 0) { redA[w] = mx0; redA[8 + w] = mx1; }
        __syncthreads();
        mx0 = redA[0]; mx1 = redA[8];
#pragma unroll
        for (int i = 1; i < 8; i++) { mx0 = fmaxf(mx0, redA[i]); mx1 = fmaxf(mx1, redA[8 + i]); }

        float s0 = 0.f, s1 = 0.f;
#pragma unroll
        for (int k = 0; k < 8; k++) {
            v0[k] = __expf(v0[k] - mx0); s0 += v0[k];
            v1[k] = __expf(v1[k] - mx1); s1 += v1[k];
        }
#pragma unroll
        for (int o = 16; o; o >>= 1) {
            s0 += __shfl_xor_sync(0xffffffffu, s0, o);
            s1 += __shfl_xor_sync(0xffffffffu, s1, o);
        }
        if (lane == 0) { redB[w] = s0; redB[8 + w] = s1; }
        __syncthreads();
        s0 = redB[0]; s1 = redB[8];
#pragma unroll
        for (int i = 1; i < 8; i++) { s0 += redB[i]; s1 += redB[8 + i]; }

        if (t == 0) {
            g_rowmax[b * NN + n]     = mx0;
            g_rowsum[b * NN + n]     = s0;
            g_rowmax[b * NN + n + 1] = mx1;
            g_rowsum[b * NN + n + 1] = s1;
        }
        float i0 = 1.0f / s0, i1 = 1.0f / s1;
#pragma unroll
        for (int k = 0; k < 8; k++) colacc[k] += v0[k] * i0;
#pragma unroll
        for (int k = 0; k < 8; k++) colacc[k] += v1[k] * i1;
        if (rp < 7) {
#pragma unroll
            for (int k = 0; k < 8; k++) { v0[k] = w0[k]; v1[k] = w1[k]; }
        }
    }
    float* part = g_selpart + ((size_t)b * 128 + blockIdx.x) * NN;
#pragma unroll
    for (int k = 0; k < 8; k++) part[t + k * 256] = colacc[k];
}

// ---------------- kernel 3b: reduce partials — cp.async staging, exact linear order -----
// 64 threads/block, 256 blocks: full SM coverage; per-column order unchanged.
#define SEL_SMEM (64 * 128 * 4)
__global__ __launch_bounds__(64) void selsum_kernel() {
    extern __shared__ float sbuf[];   // [term][col] = [128][64]
    const int b = blockIdx.y;
    const int t = threadIdx.x;
    const int m = blockIdx.x * 64 + t;
    const float* p = g_selpart + (size_t)b * 128 * NN + m;
    const uint32_t sb = smem_u32(sbuf);

#pragma unroll 16
    for (int i = 0; i < 128; i++) {
        asm volatile("cp.async.ca.shared.global [%0], [%1], 4;"
            :: "r"(sb + (uint32_t)(i * 64 + t) * 4), "l"(p + (size_t)i * NN));
    }
    asm volatile("cp.async.commit_group;" ::: "memory");
    asm volatile("cp.async.wait_group 0;" ::: "memory");

    float s = 0.f;
#pragma unroll 16
    for (int i = 0; i < 128; i++) s += sbuf[i * 64 + t];   // same linear order
    g_sel[b * NN + m] = s;
}

// ---------------- kernel 4: stable top-k via rank counting ----------------
__global__ __launch_bounds__(256) void topk_kernel() {
    __shared__ float s[NN];
    const int b = blockIdx.y;
    for (int i = threadIdx.x; i < NN; i += 256) s[i] = __ldg(&g_sel[b * NN + i]);
    __syncthreads();
    const int i  = blockIdx.x * 256 + threadIdx.x;
    const float vi = s[i];
    int rank = 0;
#pragma unroll 8
    for (int j = 0; j < NN; j++) {
        float vj = s[j];
        rank += (vj > vi) || (vj == vi && j < i);
    }
    if (rank < MM) g_idx[b * MM + rank] = i;
}

// ---------------- kernel 5: output GEMM via bf16x3 mma.sync, split-K=4 ----------------
#define ST2 72
#define OV_H 0
#define OV_L (128 * ST2 * 2)
#define OP_H (2 * 128 * ST2 * 2)
#define OP_L (OP_H + 64 * ST2 * 2)
#define O_SMEM (OP_L + 64 * ST2 * 2)

__global__ __launch_bounds__(256) void outgemm_tc_kernel() {
    extern __shared__ char osm[];
    __shared__ int   rows[64];
    __shared__ float rmax[64], rinv[64];
    const uint32_t sbase = smem_u32(osm);
    const int b = blockIdx.y, j0 = blockIdx.x * 64, z = blockIdx.z;
    const int t = threadIdx.x, lane = t & 31, wid = t >> 5;
    const int wc = wid & 3, wj = wid >> 2;
    const int g = lane >> 2, tg = lane & 3;

    if (t < 64) {
        int r   = g_idx[b * MM + j0 + t];
        rows[t] = r;
        rmax[t] = g_rowmax[b * NN + r];
        rinv[t] = 1.0f / g_rowsum[b * NN + r];
    }
    __syncthreads();

    const __nv_bfloat16* vh = g_vh + (size_t)b * C * NN;
    const __nv_bfloat16* vl = g_vl + (size_t)b * C * NN;
    const float* Eb = g_E + (size_t)b * NN * NN;

    const uint32_t laneA = (uint32_t)((lane & 15) * ST2 + (lane >> 4) * 8) * 2;
    const int l16 = lane & 15;
    const uint32_t laneB = (uint32_t)((l16 & 7) * ST2 + (l16 >> 3) * 8) * 2;

    float acc[2][4][4];
#pragma unroll
    for (int i = 0; i < 2; i++)
#pragma unroll
        for (int j = 0; j < 4; j++)
#pragma unroll
            for (int r = 0; r < 4; r++) acc[i][j][r] = 0.f;

    const int nBeg = z * (NN / 4);
    const int jj = t >> 2, q4 = t & 3;
    const float mxj = rmax[jj], ivj = rinv[jj];
    const size_t erow = (size_t)rows[jj] * NN;

    for (int n0 = nBeg; n0 < nBeg + NN / 4; n0 += 64) {
#pragma unroll
        for (int jld = 0; jld < 4; jld++) {
            int i = t + jld * 256;
            int c = i >> 3, k8 = i & 7;
            asm volatile("cp.async.cg.shared.global [%0], [%1], 16;"
                :: "r"(sbase + OV_H + (uint32_t)(c * ST2 + k8 * 8) * 2),
                   "l"(vh + (size_t)c * NN + n0 + k8 * 8));
            asm volatile("cp.async.cg.shared.global [%0], [%1], 16;"
                :: "r"(sbase + OV_L + (uint32_t)(c * ST2 + k8 * 8) * 2),
                   "l"(vl + (size_t)c * NN + n0 + k8 * 8));
        }
        asm volatile("cp.async.commit_group;" ::: "memory");

        {
            const float* Er = Eb + erow + n0 + q4 * 16;
#pragma unroll
            for (int i4 = 0; i4 < 4; i4++) {
                float4 e = *(const float4*)(Er + i4 * 4);
                float p0 = __expf(e.x - mxj) * ivj;
                float p1 = __expf(e.y - mxj) * ivj;
                float p2 = __expf(e.z - mxj) * ivj;
                float p3 = __expf(e.w - mxj) * ivj;
                __nv_bfloat16 h0 = __float2bfloat16_rn(p0);
                __nv_bfloat16 h1 = __float2bfloat16_rn(p1);
                __nv_bfloat16 h2 = __float2bfloat16_rn(p2);
                __nv_bfloat16 h3 = __float2bfloat16_rn(p3);
                __nv_bfloat16 l0 = __float2bfloat16_rn(p0 - __bfloat162float(h0));
                __nv_bfloat16 l1 = __float2bfloat16_rn(p1 - __bfloat162float(h1));
                __nv_bfloat16 l2 = __float2bfloat16_rn(p2 - __bfloat162float(h2));
                __nv_bfloat16 l3 = __float2bfloat16_rn(p3 - __bfloat162float(h3));
                uint32_t off = (uint32_t)(jj * ST2 + q4 * 16 + i4 * 4) * 2;
                *(__nv_bfloat162*)(osm + OP_H + off)     = __nv_bfloat162(h0, h1);
                *(__nv_bfloat162*)(osm + OP_H + off + 4) = __nv_bfloat162(h2, h3);
                *(__nv_bfloat162*)(osm + OP_L + off)     = __nv_bfloat162(l0, l1);
                *(__nv_bfloat162*)(osm + OP_L + off + 4) = __nv_bfloat162(l2, l3);
            }
        }
        asm volatile("cp.async.wait_group 0;" ::: "memory");
        __syncthreads();

#pragma unroll
        for (int k0 = 0; k0 < 64; k0 += 16) {
            uint32_t bh[4][2], bl[4][2];
#pragma unroll
            for (int nj = 0; nj < 4; nj++) {
                uint32_t boff = (uint32_t)((wj * 32 + nj * 8) * ST2 + k0) * 2 + laneB;
                ldsm_x2(bh[nj], sbase + OP_H + boff);
                ldsm_x2(bl[nj], sbase + OP_L + boff);
            }
#pragma unroll
            for (int mi = 0; mi < 2; mi++) {
                uint32_t aoff = (uint32_t)((wc * 32 + mi * 16) * ST2 + k0) * 2 + laneA;
                uint32_t ah[4], al[4];
                ldsm_x4(ah, sbase + OV_H + aoff);
                ldsm_x4(al, sbase + OV_L + aoff);
#pragma unroll
                for (int nj = 0; nj < 4; nj++) {
                    mma_bf16(acc[mi][nj], ah, bh[nj]);
                    mma_bf16(acc[mi][nj], ah, bl[nj]);
                    mma_bf16(acc[mi][nj], al, bh[nj]);
                }
            }
        }
        __syncthreads();
    }

    float* op = g_outpart[z];
#pragma unroll
    for (int mi = 0; mi < 2; mi++) {
        int c = wc * 32 + mi * 16 + g;
#pragma unroll
        for (int nj = 0; nj < 4; nj++) {
            int col = j0 + wj * 32 + nj * 8 + tg * 2;
            *(float2*)&op[((size_t)b * C + c) * MM + col] =
                make_float2(acc[mi][nj][0], acc[mi][nj][1]);
            *(float2*)&op[((size_t)b * C + c + 8) * MM + col] =
                make_float2(acc[mi][nj][2], acc[mi][nj][3]);
        }
    }
}

// ---------------- kernel 6: reduce split-K partials ----------------
__global__ __launch_bounds__(256) void outred_kernel(float* __restrict__ out) {
    const int i = blockIdx.x * 256 + threadIdx.x;
    out[i] = g_outpart[0][i] + g_outpart[1][i] + g_outpart[2][i] + g_outpart[3][i];
}

// ---------------- launch ----------------
extern "C" void kernel_launch(void* const* d_in, const int* in_sizes, int n_in,
                              void* d_out, int out_size) {
    const float* x  = (const float*)d_in[0];
    const float* Wq = (const float*)d_in[1];
    const float* Wk = (const float*)d_in[2];
    const float* Wv = (const float*)d_in[3];
    float* out = (float*)d_out;

    cudaFuncSetAttribute(qkv_kernel, cudaFuncAttributeMaxDynamicSharedMemorySize, 96 * 1024);
    cudaFuncSetAttribute(energy_bf16_kernel, cudaFuncAttributeMaxDynamicSharedMemorySize, E_SMEM);
    cudaFuncSetAttribute(outgemm_tc_kernel, cudaFuncAttributeMaxDynamicSharedMemorySize, O_SMEM);
    cudaFuncSetAttribute(selsum_kernel, cudaFuncAttributeMaxDynamicSharedMemorySize, SEL_SMEM);

    qkv_kernel<<<dim3(NN / 64, B, 3), 256, 96 * 1024>>>(x, Wq, Wk, Wv);
    energy_bf16_kernel<<<dim3(NN / 128, NN / 128, B), 512, E_SMEM>>>();
    softscan_kernel<<<dim3(NN / 16, B), 256>>>();
    selsum_kernel<<<dim3(NN / 64, B), 64, SEL_SMEM>>>();
    topk_kernel<<<dim3(NN / 256, B), 256>>>();
    outgemm_tc_kernel<<<dim3(MM / 64, B, 4), 256, O_SMEM>>>();
    outred_kernel<<<(B * C * MM) / 256, 256>>>(out);
}